// round 11
// baseline (speedup 1.0000x reference)
#include <cuda_runtime.h>

#define SLEN 64
#define BATCH 64
#define EDIM 256
#define G4 2048
#define OUTV 6000
#define DSTEPS 63
#define NCTA 128
#define TPB 256
#define PART (BATCH * G4)

typedef unsigned long long u64;

// ---------------- static device scratch ----------------
__device__ float g_Xenc[SLEN * PART];
__device__ float g_Xdec[DSTEPS * PART];
__device__ float g_embS[SLEN * BATCH * EDIM];
__device__ float g_embT[DSTEPS * BATCH * EDIM];
__device__ float g_encouts[SLEN * BATCH * 512];
__device__ float g_dech1[DSTEPS * BATCH * 512];
__device__ float g_partA[8 * PART];
__device__ float g_partB[8 * PART];
__device__ float g_Wenc0T[512 * 2048];
__device__ float g_Wenc1T[1024 * 2048];
__device__ float g_Wdec0T[1024 * 2048];
__device__ float g_Wdec1T[1024 * 2048];
__device__ float g_encA1T[1024 * 64];
__device__ float g_decA0T[1024 * 64];
__device__ float g_decA1T[1024 * 64];
__device__ float g_c0[BATCH * 512];
__device__ float g_c1[BATCH * 512];
__device__ unsigned g_flags[NCTA];
__device__ unsigned g_gen2;

// ---------------- f32x2 helpers ----------------
static __device__ __forceinline__ u64 splat2(float x) {
    u64 r; asm("mov.b64 %0, {%1, %1};" : "=l"(r) : "f"(x)); return r;
}
static __device__ __forceinline__ u64 ffma2(u64 a, u64 b, u64 c) {
    u64 d; asm("fma.rn.f32x2 %0, %1, %2, %3;" : "=l"(d) : "l"(a), "l"(b), "l"(c)); return d;
}
static __device__ __forceinline__ float2 unpack2(u64 v) {
    float2 r; asm("mov.b64 {%0, %1}, %2;" : "=f"(r.x), "=f"(r.y) : "l"(v)); return r;
}
static __device__ __forceinline__ float sigmf(float x) {
    return 1.0f / (1.0f + __expf(-x));
}

// ---------------- flag-based grid barrier (parallel arrival, no atomics) ----------------
// Each CTA releases its own flag slot; CTA0's threads 1..127 poll the 127
// distinct flags in parallel (independent LTS slices), then thread 0 releases
// the generation counter that everyone else polls. ~2 L2 round-trips total.
static __device__ __forceinline__ void gbar(unsigned& gen) {
    gen++;
    __syncthreads();
    if (blockIdx.x == 0) {
        if (threadIdx.x > 0 && threadIdx.x < NCTA) {
            unsigned v;
            do {
                asm volatile("ld.acquire.gpu.u32 %0, [%1];"
                             : "=r"(v) : "l"(&g_flags[threadIdx.x]) : "memory");
            } while (v != gen);
        }
        __syncthreads();
        if (threadIdx.x == 0)
            asm volatile("st.release.gpu.u32 [%0], %1;" :: "l"(&g_gen2), "r"(gen) : "memory");
    } else {
        if (threadIdx.x == 0) {
            asm volatile("st.release.gpu.u32 [%0], %1;"
                         :: "l"(&g_flags[blockIdx.x]), "r"(gen) : "memory");
            unsigned v;
            do {
                asm volatile("ld.acquire.gpu.u32 %0, [%1];" : "=r"(v) : "l"(&g_gen2) : "memory");
            } while (v != gen);
        }
        __syncthreads();
    }
}

// ---------------- in-kernel tile GEMM: 64 rows x 128 cols (R7 v3) ----------------
// part[r][col0+c] = sum_{k in [k0,k0+klen)} AT[k][r] * WT[k][col0+c]
static __device__ __forceinline__ void tile_gemm(
    float (*Ash)[64], float (*Wsh)[128],
    const float* __restrict__ AT, const float* __restrict__ WT,
    int k0, int klen, int col0, float* __restrict__ part)
{
    const int t = threadIdx.x;
    const int rg = (t & 15) * 4;   // 4 rows
    const int cg = (t >> 4) * 8;   // 8 cols = 4 pairs
    u64 acc[4][4];
#pragma unroll
    for (int r = 0; r < 4; r++)
#pragma unroll
        for (int c = 0; c < 4; c++) acc[r][c] = 0ull;

    const int ka = t >> 4, ca = (t & 15) * 4;          // A fill: 1 float4
    const int kw0 = t >> 5, cw0 = (t & 31) * 4;        // W fill: 2 float4
    const int kw1 = (t + 256) >> 5, cw1 = ((t + 256) & 31) * 4;
    float4 av, wv0, wv1;
    av  = __ldcg((const float4*)&AT[(size_t)(k0 + ka) * 64 + ca]);
    wv0 = *(const float4*)&WT[(size_t)(k0 + kw0) * 2048 + col0 + cw0];
    wv1 = *(const float4*)&WT[(size_t)(k0 + kw1) * 2048 + col0 + cw1];

    for (int kb = 0; kb < klen; kb += 16) {
        *(float4*)&Ash[ka][ca] = av;
        *(float4*)&Wsh[kw0][cw0] = wv0;
        *(float4*)&Wsh[kw1][cw1] = wv1;
        __syncthreads();
        if (kb + 16 < klen) {
            int kn = k0 + kb + 16;
            av  = __ldcg((const float4*)&AT[(size_t)(kn + ka) * 64 + ca]);
            wv0 = *(const float4*)&WT[(size_t)(kn + kw0) * 2048 + col0 + cw0];
            wv1 = *(const float4*)&WT[(size_t)(kn + kw1) * 2048 + col0 + cw1];
        }
#pragma unroll
        for (int kk = 0; kk < 16; kk++) {
            float4 a4 = *(const float4*)&Ash[kk][rg];
            u64 as0 = splat2(a4.x), as1 = splat2(a4.y), as2 = splat2(a4.z), as3 = splat2(a4.w);
            const u64* wd = (const u64*)&Wsh[kk][cg];
            u64 w0 = wd[0], w1 = wd[1], w2 = wd[2], w3 = wd[3];
            acc[0][0] = ffma2(as0, w0, acc[0][0]); acc[0][1] = ffma2(as0, w1, acc[0][1]);
            acc[0][2] = ffma2(as0, w2, acc[0][2]); acc[0][3] = ffma2(as0, w3, acc[0][3]);
            acc[1][0] = ffma2(as1, w0, acc[1][0]); acc[1][1] = ffma2(as1, w1, acc[1][1]);
            acc[1][2] = ffma2(as1, w2, acc[1][2]); acc[1][3] = ffma2(as1, w3, acc[1][3]);
            acc[2][0] = ffma2(as2, w0, acc[2][0]); acc[2][1] = ffma2(as2, w1, acc[2][1]);
            acc[2][2] = ffma2(as2, w2, acc[2][2]); acc[2][3] = ffma2(as2, w3, acc[2][3]);
            acc[3][0] = ffma2(as3, w0, acc[3][0]); acc[3][1] = ffma2(as3, w1, acc[3][1]);
            acc[3][2] = ffma2(as3, w2, acc[3][2]); acc[3][3] = ffma2(as3, w3, acc[3][3]);
        }
        __syncthreads();
    }
#pragma unroll
    for (int r = 0; r < 4; r++) {
        float2 v0 = unpack2(acc[r][0]), v1 = unpack2(acc[r][1]);
        float2 v2 = unpack2(acc[r][2]), v3 = unpack2(acc[r][3]);
        float* d = &part[(size_t)(rg + r) * G4 + col0 + cg];
        *(float4*)d = make_float4(v0.x, v0.y, v1.x, v1.y);
        *(float4*)(d + 4) = make_float4(v2.x, v2.y, v3.x, v3.y);
    }
}

// ---------------- LSTM pointwise (one h-element per thread) ----------------
static __device__ __forceinline__ void pointwise(
    const float* __restrict__ p1, int n1, const float* __restrict__ p2, int n2,
    const float* __restrict__ xadd,
    const float* __restrict__ bih, const float* __restrict__ bhh,
    float* __restrict__ c, float* __restrict__ hT1, float* __restrict__ hT2,
    float* __restrict__ hflat)
{
    int idx = blockIdx.x * TPB + threadIdx.x;  // 0..32767
    int b = idx >> 9, j = idx & 511;
    float g[4];
#pragma unroll
    for (int gi = 0; gi < 4; gi++) {
        int col = gi * 512 + j;
        size_t off = (size_t)b * G4 + col;
        float v = bih[col] + bhh[col];
        if (xadd) v += xadd[off];
        for (int s = 0; s < n1; s++) v += __ldcg(&p1[(size_t)s * PART + off]);
        for (int s = 0; s < n2; s++) v += __ldcg(&p2[(size_t)s * PART + off]);
        g[gi] = v;
    }
    float ig = sigmf(g[0]), fg = sigmf(g[1]), tg = tanhf(g[2]), og = sigmf(g[3]);
    float cn = fg * c[idx] + ig * tg;
    c[idx] = cn;
    float h = og * tanhf(cn);
    hT1[j * 64 + b] = h;
    if (hT2) hT2[j * 64 + b] = h;
    if (hflat) hflat[(size_t)b * 512 + j] = h;
}

// ---------------- attention (CTA = batch row b) ----------------
static __device__ __forceinline__ void attention(int b, float* hsh, float* ssh, float* ash) {
    int tid = threadIdx.x;
    for (int k = tid; k < 512; k += TPB) hsh[k] = __ldcg(&g_decA1T[(512 + k) * 64 + b]);
    __syncthreads();
    int w = tid >> 5, lane = tid & 31;
    for (int s = w; s < 64; s += 8) {
        const float* e = g_encouts + (size_t)s * 32768 + (size_t)b * 512;
        float d = 0.f;
#pragma unroll 4
        for (int k = lane; k < 512; k += 32) d += e[k] * hsh[k];
#pragma unroll
        for (int o = 16; o; o >>= 1) d += __shfl_down_sync(0xffffffffu, d, o);
        if (!lane) ssh[s] = d;
    }
    __syncthreads();
    if (tid < 32) {
        float s0 = ssh[tid], s1 = ssh[tid + 32];
        float m = fmaxf(s0, s1);
#pragma unroll
        for (int o = 16; o; o >>= 1) m = fmaxf(m, __shfl_xor_sync(0xffffffffu, m, o));
        float e0 = __expf(s0 - m), e1 = __expf(s1 - m);
        float sum = e0 + e1;
#pragma unroll
        for (int o = 16; o; o >>= 1) sum += __shfl_xor_sync(0xffffffffu, sum, o);
        float inv = 1.f / sum;
        ash[tid] = e0 * inv;
        ash[tid + 32] = e1 * inv;
    }
    __syncthreads();
    for (int j = tid; j < 512; j += TPB) {
        float acc = 0.f;
#pragma unroll 8
        for (int s = 0; s < 64; s++)
            acc += ash[s] * g_encouts[(size_t)s * 32768 + (size_t)b * 512 + j];
        g_decA0T[j * 64 + b] = acc;
    }
    __syncthreads();
}

// ---------------- persistent recurrence kernel ----------------
__global__ void __launch_bounds__(TPB, 1) recurrent(
    const float* __restrict__ ebih0, const float* __restrict__ ebhh0,
    const float* __restrict__ ebih1, const float* __restrict__ ebhh1,
    const float* __restrict__ dbih0, const float* __restrict__ dbhh0,
    const float* __restrict__ dbih1, const float* __restrict__ dbhh1)
{
    __shared__ __align__(16) float Ash[16][64];
    __shared__ __align__(16) float Wsh[16][128];
    __shared__ float hsh[512];
    __shared__ float ssh[64];
    __shared__ float ashm[64];
    const int bid = blockIdx.x;
    const int gid = bid * TPB + threadIdx.x;   // 0..32767

    // replay-safe generation base (flags retain last run's value; gen continues)
    unsigned gen;
    asm volatile("ld.acquire.gpu.u32 %0, [%1];" : "=r"(gen) : "l"(&g_gen2) : "memory");

    // zero initial states (fresh each launch/replay)
    g_encA1T[gid] = 0.f;
    g_encA1T[gid + 32768] = 0.f;
    g_c0[gid] = 0.f;
    g_c1[gid] = 0.f;
    gbar(gen);

    const int ks = bid >> 4;                   // 0..7
    const int colJ = (bid & 15) * 128;

    // prime: encoder L0 recurrent gemm for t=0 (zero state)
    tile_gemm(Ash, Wsh, g_encA1T, g_Wenc0T, ks * 64, 64, colJ, g_partB + (size_t)ks * PART);
    gbar(gen);

    // ---- encoder: 2 phases per step ----
    for (int st = 0; st < SLEN; st++) {
        pointwise(g_partB, 8, nullptr, 0, g_Xenc + (size_t)st * PART, ebih0, ebhh0,
                  g_c0, g_encA1T, nullptr, nullptr);
        if (st > 0)
            pointwise(g_partA, 8, nullptr, 0, nullptr, ebih1, ebhh1,
                      g_c1, g_encA1T + 512 * 64, nullptr,
                      g_encouts + (size_t)(st - 1) * 32768);
        gbar(gen);
        tile_gemm(Ash, Wsh, g_encA1T, g_Wenc1T, ks * 128, 128, colJ, g_partA + (size_t)ks * PART);
        if (st < SLEN - 1)
            tile_gemm(Ash, Wsh, g_encA1T, g_Wenc0T, ks * 64, 64, colJ, g_partB + (size_t)ks * PART);
        gbar(gen);
    }
    // final pw1(63)
    pointwise(g_partA, 8, nullptr, 0, nullptr, ebih1, ebhh1,
              g_c1, g_encA1T + 512 * 64, nullptr, g_encouts + (size_t)(SLEN - 1) * 32768);
    gbar(gen);

    // transition: encoder final states -> decoder layout
    {
        int j = gid >> 6, b = gid & 63;
        float h0 = __ldcg(&g_encA1T[j * 64 + b]);
        float h1 = __ldcg(&g_encA1T[(512 + j) * 64 + b]);
        g_decA0T[(512 + j) * 64 + b] = h0;
        g_decA1T[j * 64 + b] = h0;
        g_decA1T[(512 + j) * 64 + b] = h1;
    }
    gbar(gen);

    for (int st = 0; st < DSTEPS; st++) {
        // phase A: attention (CTAs 0..63) || L0 gemm h0-half K=[512,1024) (CTAs 64..127)
        if (bid < 64) attention(bid, hsh, ssh, ashm);
        else tile_gemm(Ash, Wsh, g_decA0T, g_Wdec0T, ks * 128, 128, colJ,
                       g_partB + (size_t)ks * PART);
        gbar(gen);
        // phase B: all CTAs, ctx-half K=[0,512)
        tile_gemm(Ash, Wsh, g_decA0T, g_Wdec0T, ks * 64, 64, colJ, g_partA + (size_t)ks * PART);
        gbar(gen);
        // phase C: pointwise L0 (sum partA[0..7] + partB[4..7])
        pointwise(g_partA, 8, g_partB + 4 * (size_t)PART, 4,
                  g_Xdec + (size_t)st * PART, dbih0, dbhh0,
                  g_c0, g_decA0T + 512 * 64, g_decA1T, nullptr);
        gbar(gen);
        // phase D: L1 gemm K=1024
        tile_gemm(Ash, Wsh, g_decA1T, g_Wdec1T, ks * 128, 128, colJ, g_partB + (size_t)ks * PART);
        gbar(gen);
        // phase E: pointwise L1
        pointwise(g_partB, 8, nullptr, 0, nullptr, dbih1, dbhh1,
                  g_c1, g_decA1T + 512 * 64, nullptr, g_dech1 + (size_t)st * 32768);
        gbar(gen);
    }
}

// ---------------- prologue / epilogue kernels ----------------
__global__ void zero_kernel(float* __restrict__ p, int n) {
    int i = blockIdx.x * blockDim.x + threadIdx.x;
    if (i < n) p[i] = 0.0f;
}

// fused 7-way transpose pack: dst[(dstk0+k)*2048 + r] = src[r*lds + coloff + k]
__global__ void transpose_all(
    const float* __restrict__ eWhh0, const float* __restrict__ eWih1, const float* __restrict__ eWhh1,
    const float* __restrict__ dWih0, const float* __restrict__ dWhh0,
    const float* __restrict__ dWih1, const float* __restrict__ dWhh1,
    float* __restrict__ W0T, float* __restrict__ W1T,
    float* __restrict__ D0T, float* __restrict__ D1T)
{
    __shared__ float tile[32][33];
    const float* src; int lds = 512, coloff = 0, dstk0 = 0; float* dst;
    switch (blockIdx.z) {
        case 0: src = eWhh0; dst = W0T; break;
        case 1: src = eWih1; dst = W1T; break;
        case 2: src = eWhh1; dst = W1T; dstk0 = 512; break;
        case 3: src = dWih0; dst = D0T; lds = 768; coloff = 256; break;
        case 4: src = dWhh0; dst = D0T; dstk0 = 512; break;
        case 5: src = dWih1; dst = D1T; break;
        default: src = dWhh1; dst = D1T; dstk0 = 512; break;
    }
    int rb = blockIdx.x * 32, kb = blockIdx.y * 32;
    int tx = threadIdx.x & 31, ty = threadIdx.x >> 5;
#pragma unroll
    for (int i = 0; i < 4; i++)
        tile[ty + i * 8][tx] = src[(size_t)(rb + ty + i * 8) * lds + coloff + kb + tx];
    __syncthreads();
#pragma unroll
    for (int i = 0; i < 4; i++)
        dst[(size_t)(dstk0 + kb + ty + i * 8) * 2048 + rb + tx] = tile[tx][ty + i * 8];
}

__global__ void gather_embed(const int* __restrict__ src, const int* __restrict__ trg,
                             const float* __restrict__ enc_emb, const float* __restrict__ dec_emb) {
    int row = blockIdx.x;
    int t4 = threadIdx.x;
    if (row < SLEN * BATCH) {
        int tok = src[row];
        reinterpret_cast<float4*>(g_embS + (size_t)row * EDIM)[t4] =
            reinterpret_cast<const float4*>(enc_emb + (size_t)tok * EDIM)[t4];
    } else {
        int r = row - SLEN * BATCH;
        int tok = trg[r];
        reinterpret_cast<float4*>(g_embT + (size_t)r * EDIM)[t4] =
            reinterpret_cast<const float4*>(dec_emb + (size_t)tok * EDIM)[t4];
    }
}

// ---------------- big GEMM core (R7 f32x2 version) ----------------
static __device__ __forceinline__ void gemm_core(
    const float* __restrict__ A, int lda, const float* __restrict__ W, int ldw,
    const float* __restrict__ bias, float* __restrict__ C, int ldc,
    int M, int N, int K, int bx, int by)
{
    __shared__ __align__(16) float Ash[16][132];
    __shared__ __align__(16) float Wsh[16][132];
    int row0 = by * 128, col0 = bx * 128;
    int tid = threadIdx.x;
    int tx = tid & 15, ty = tid >> 4;
    int lr = tid >> 2, lk4 = (tid & 3) * 4;
    u64 acc[4][8];
#pragma unroll
    for (int p = 0; p < 4; p++)
#pragma unroll
        for (int j = 0; j < 8; j++) acc[p][j] = 0ull;

    float4 avr[2], wvr[2];
#pragma unroll
    for (int h = 0; h < 2; h++) {
        int rr = lr + h * 64;
        int r = row0 + rr, c = col0 + rr;
        avr[h] = (r < M) ? *(const float4*)&A[(size_t)r * lda + lk4] : make_float4(0, 0, 0, 0);
        wvr[h] = (c < N) ? *(const float4*)&W[(size_t)c * ldw + lk4] : make_float4(0, 0, 0, 0);
    }
    for (int kb = 0; kb < K; kb += 16) {
#pragma unroll
        for (int h = 0; h < 2; h++) {
            int rr = lr + h * 64;
            Ash[lk4 + 0][rr] = avr[h].x; Ash[lk4 + 1][rr] = avr[h].y;
            Ash[lk4 + 2][rr] = avr[h].z; Ash[lk4 + 3][rr] = avr[h].w;
            Wsh[lk4 + 0][rr] = wvr[h].x; Wsh[lk4 + 1][rr] = wvr[h].y;
            Wsh[lk4 + 2][rr] = wvr[h].z; Wsh[lk4 + 3][rr] = wvr[h].w;
        }
        __syncthreads();
        if (kb + 16 < K) {
            int kn = kb + 16;
#pragma unroll
            for (int h = 0; h < 2; h++) {
                int rr = lr + h * 64;
                int r = row0 + rr, c = col0 + rr;
                avr[h] = (r < M) ? *(const float4*)&A[(size_t)r * lda + kn + lk4] : make_float4(0, 0, 0, 0);
                wvr[h] = (c < N) ? *(const float4*)&W[(size_t)c * ldw + kn + lk4] : make_float4(0, 0, 0, 0);
            }
        }
#pragma unroll
        for (int kk = 0; kk < 16; kk++) {
            const u64* ap = (const u64*)&Ash[kk][ty * 8];
            u64 a0 = ap[0], a1 = ap[1], a2 = ap[2], a3 = ap[3];
            float4 w0 = *(const float4*)&Wsh[kk][tx * 8];
            float4 w1 = *(const float4*)&Wsh[kk][tx * 8 + 4];
            u64 ws[8];
            ws[0] = splat2(w0.x); ws[1] = splat2(w0.y); ws[2] = splat2(w0.z); ws[3] = splat2(w0.w);
            ws[4] = splat2(w1.x); ws[5] = splat2(w1.y); ws[6] = splat2(w1.z); ws[7] = splat2(w1.w);
#pragma unroll
            for (int j = 0; j < 8; j++) {
                acc[0][j] = ffma2(a0, ws[j], acc[0][j]);
                acc[1][j] = ffma2(a1, ws[j], acc[1][j]);
                acc[2][j] = ffma2(a2, ws[j], acc[2][j]);
                acc[3][j] = ffma2(a3, ws[j], acc[3][j]);
            }
        }
        __syncthreads();
    }
#pragma unroll
    for (int p = 0; p < 4; p++) {
        float2 v[8];
#pragma unroll
        for (int j = 0; j < 8; j++) v[j] = unpack2(acc[p][j]);
        int r = row0 + ty * 8 + p * 2;
        if (r < M) {
#pragma unroll
            for (int j = 0; j < 8; j++) {
                int c = col0 + tx * 8 + j;
                if (c < N) C[(size_t)r * ldc + c] = v[j].x + (bias ? bias[c] : 0.0f);
            }
        }
        if (r + 1 < M) {
#pragma unroll
            for (int j = 0; j < 8; j++) {
                int c = col0 + tx * 8 + j;
                if (c < N) C[(size_t)(r + 1) * ldc + c] = v[j].y + (bias ? bias[c] : 0.0f);
            }
        }
    }
}

__global__ void __launch_bounds__(256) big_gemm(
    const float* __restrict__ A, int lda, const float* __restrict__ W, int ldw,
    const float* __restrict__ bias, float* __restrict__ C, int ldc,
    int M, int N, int K)
{
    gemm_core(A, lda, W, ldw, bias, C, ldc, M, N, K, blockIdx.x, blockIdx.y);
}

// fused projection gemm: z=0 encoder, z=1 decoder
__global__ void __launch_bounds__(256) proj_gemm(
    const float* __restrict__ embS, const float* __restrict__ eWih0,
    const float* __restrict__ embT, const float* __restrict__ dWih0,
    float* __restrict__ Xenc, float* __restrict__ Xdec)
{
    if (blockIdx.z == 0)
        gemm_core(embS, EDIM, eWih0, EDIM, nullptr, Xenc, G4,
                  SLEN * BATCH, G4, EDIM, blockIdx.x, blockIdx.y);
    else
        gemm_core(embT, EDIM, dWih0, 768, nullptr, Xdec, G4,
                  DSTEPS * BATCH, G4, EDIM, blockIdx.x, blockIdx.y);
}

// ---------------- host ----------------
extern "C" void kernel_launch(void* const* d_in, const int* in_sizes, int n_in,
                              void* d_out, int out_size) {
    const int* src = (const int*)d_in[0];
    const int* trg = (const int*)d_in[1];
    const float* enc_emb = (const float*)d_in[2];
    const float* eWih0 = (const float*)d_in[3];
    const float* eWhh0 = (const float*)d_in[4];
    const float* ebih0 = (const float*)d_in[5];
    const float* ebhh0 = (const float*)d_in[6];
    const float* eWih1 = (const float*)d_in[7];
    const float* eWhh1 = (const float*)d_in[8];
    const float* ebih1 = (const float*)d_in[9];
    const float* ebhh1 = (const float*)d_in[10];
    const float* dec_emb = (const float*)d_in[11];
    const float* dWih0 = (const float*)d_in[12];
    const float* dWhh0 = (const float*)d_in[13];
    const float* dbih0 = (const float*)d_in[14];
    const float* dbhh0 = (const float*)d_in[15];
    const float* dWih1 = (const float*)d_in[16];
    const float* dWhh1 = (const float*)d_in[17];
    const float* dbih1 = (const float*)d_in[18];
    const float* dbhh1 = (const float*)d_in[19];
    const float* fcW = (const float*)d_in[20];
    const float* fcb = (const float*)d_in[21];
    float* out = (float*)d_out;

    float *Xenc, *Xdec, *embS, *embT, *dech1;
    float *W0T, *W1T, *D0T, *D1T;
    cudaGetSymbolAddress((void**)&Xenc, g_Xenc);
    cudaGetSymbolAddress((void**)&Xdec, g_Xdec);
    cudaGetSymbolAddress((void**)&embS, g_embS);
    cudaGetSymbolAddress((void**)&embT, g_embT);
    cudaGetSymbolAddress((void**)&dech1, g_dech1);
    cudaGetSymbolAddress((void**)&W0T, g_Wenc0T);
    cudaGetSymbolAddress((void**)&W1T, g_Wenc1T);
    cudaGetSymbolAddress((void**)&D0T, g_Wdec0T);
    cudaGetSymbolAddress((void**)&D1T, g_Wdec1T);

    zero_kernel<<<(BATCH * OUTV + 255) / 256, 256>>>(out, BATCH * OUTV);
    gather_embed<<<SLEN * BATCH + DSTEPS * BATCH, 64>>>(src, trg, enc_emb, dec_emb);
    transpose_all<<<dim3(64, 16, 7), 256>>>(eWhh0, eWih1, eWhh1, dWih0, dWhh0, dWih1, dWhh1,
                                            W0T, W1T, D0T, D1T);
    proj_gemm<<<dim3(16, 32, 2), 256>>>(embS, eWih0, embT, dWih0, Xenc, Xdec);
    recurrent<<<NCTA, TPB>>>(ebih0, ebhh0, ebih1, ebhh1, dbih0, dbhh0, dbih1, dbhh1);
    big_gemm<<<dim3(47, 32), 256>>>(dech1, 512, fcW, 512, fcb,
                                    out + (size_t)BATCH * OUTV, OUTV,
                                    DSTEPS * BATCH, OUTV, 512);
}

// round 12
// speedup vs baseline: 1.0176x; 1.0176x over previous
#include <cuda_runtime.h>

#define SLEN 64
#define BATCH 64
#define EDIM 256
#define G4 2048
#define OUTV 6000
#define DSTEPS 63
#define NCTA 128
#define TPB 256
#define PART (BATCH * G4)

typedef unsigned long long u64;

// ---------------- static device scratch ----------------
__device__ float g_Xenc[SLEN * PART];
__device__ float g_Xdec[DSTEPS * PART];
__device__ float g_embS[SLEN * BATCH * EDIM];
__device__ float g_embT[DSTEPS * BATCH * EDIM];
__device__ float g_encouts[SLEN * BATCH * 512];
__device__ float g_dech1[DSTEPS * BATCH * 512];
__device__ float g_partA[8 * PART];
__device__ float g_partB[8 * PART];
__device__ float g_Wenc0T[512 * 2048];
__device__ float g_Wenc1T[1024 * 2048];
__device__ float g_Wdec0T[1024 * 2048];
__device__ float g_Wdec1T[1024 * 2048];
__device__ float g_encA1T[1024 * 64];
__device__ float g_decA0T[1024 * 64];
__device__ float g_decA1T[1024 * 64];
__device__ float g_c0[BATCH * 512];
__device__ float g_c1[BATCH * 512];
__device__ unsigned g_bar_cnt;
__device__ unsigned g_bar_gen;

// ---------------- f32x2 helpers ----------------
static __device__ __forceinline__ u64 splat2(float x) {
    u64 r; asm("mov.b64 %0, {%1, %1};" : "=l"(r) : "f"(x)); return r;
}
static __device__ __forceinline__ u64 ffma2(u64 a, u64 b, u64 c) {
    u64 d; asm("fma.rn.f32x2 %0, %1, %2, %3;" : "=l"(d) : "l"(a), "l"(b), "l"(c)); return d;
}
static __device__ __forceinline__ float2 unpack2(u64 v) {
    float2 r; asm("mov.b64 {%0, %1}, %2;" : "=f"(r.x), "=f"(r.y) : "l"(v)); return r;
}
static __device__ __forceinline__ float sigmf(float x) {
    return 1.0f / (1.0f + __expf(-x));
}

// ---------------- grid barrier (atomic acq/rel — best measured) ----------------
static __device__ __forceinline__ void gbar() {
    __syncthreads();
    if (threadIdx.x == 0) {
        unsigned gen;
        asm volatile("ld.acquire.gpu.u32 %0, [%1];" : "=r"(gen) : "l"(&g_bar_gen) : "memory");
        unsigned prev;
        asm volatile("atom.acq_rel.gpu.add.u32 %0, [%1], %2;"
                     : "=r"(prev) : "l"(&g_bar_cnt), "r"(1u) : "memory");
        if (prev == NCTA - 1) {
            asm volatile("st.relaxed.gpu.u32 [%0], %1;" :: "l"(&g_bar_cnt), "r"(0u) : "memory");
            asm volatile("st.release.gpu.u32 [%0], %1;" :: "l"(&g_bar_gen), "r"(gen + 1u) : "memory");
        } else {
            unsigned cur;
            do {
                asm volatile("ld.acquire.gpu.u32 %0, [%1];" : "=r"(cur) : "l"(&g_bar_gen) : "memory");
            } while (cur == gen);
        }
    }
    __syncthreads();
}

// ---------------- tile GEMM: 64 rows x 128 cols, double-buffered smem ----------------
// Ash has 2 stages of 16 k-rows: rows [0,16) and [16,32). Same for Wsh.
// One __syncthreads per k-block (between STS and compute).
static __device__ __forceinline__ void tile_gemm(
    float (*Ash)[64], float (*Wsh)[128],
    const float* __restrict__ AT, const float* __restrict__ WT,
    int k0, int klen, int col0, float* __restrict__ part)
{
    const int t = threadIdx.x;
    const int rg = (t & 15) * 4;   // 4 rows
    const int cg = (t >> 4) * 8;   // 8 cols = 4 pairs
    u64 acc[4][4];
#pragma unroll
    for (int r = 0; r < 4; r++)
#pragma unroll
        for (int c = 0; c < 4; c++) acc[r][c] = 0ull;

    const int ka = t >> 4, ca = (t & 15) * 4;          // A fill: 1 float4
    const int kw0 = t >> 5, cw0 = (t & 31) * 4;        // W fill: 2 float4
    const int kw1 = (t + 256) >> 5, cw1 = ((t + 256) & 31) * 4;
    float4 av, wv0, wv1;
    av  = __ldcg((const float4*)&AT[(size_t)(k0 + ka) * 64 + ca]);
    wv0 = *(const float4*)&WT[(size_t)(k0 + kw0) * 2048 + col0 + cw0];
    wv1 = *(const float4*)&WT[(size_t)(k0 + kw1) * 2048 + col0 + cw1];

    const int nkb = klen >> 4;
    for (int i = 0; i < nkb; i++) {
        const int s = (i & 1) << 4;
        *(float4*)&Ash[s + ka][ca] = av;
        *(float4*)&Wsh[s + kw0][cw0] = wv0;
        *(float4*)&Wsh[s + kw1][cw1] = wv1;
        __syncthreads();
        if (i + 1 < nkb) {
            int kn = k0 + (i + 1) * 16;
            av  = __ldcg((const float4*)&AT[(size_t)(kn + ka) * 64 + ca]);
            wv0 = *(const float4*)&WT[(size_t)(kn + kw0) * 2048 + col0 + cw0];
            wv1 = *(const float4*)&WT[(size_t)(kn + kw1) * 2048 + col0 + cw1];
        }
#pragma unroll
        for (int kk = 0; kk < 16; kk++) {
            float4 a4 = *(const float4*)&Ash[s + kk][rg];
            u64 as0 = splat2(a4.x), as1 = splat2(a4.y), as2 = splat2(a4.z), as3 = splat2(a4.w);
            const u64* wd = (const u64*)&Wsh[s + kk][cg];
            u64 w0 = wd[0], w1 = wd[1], w2 = wd[2], w3 = wd[3];
            acc[0][0] = ffma2(as0, w0, acc[0][0]); acc[0][1] = ffma2(as0, w1, acc[0][1]);
            acc[0][2] = ffma2(as0, w2, acc[0][2]); acc[0][3] = ffma2(as0, w3, acc[0][3]);
            acc[1][0] = ffma2(as1, w0, acc[1][0]); acc[1][1] = ffma2(as1, w1, acc[1][1]);
            acc[1][2] = ffma2(as1, w2, acc[1][2]); acc[1][3] = ffma2(as1, w3, acc[1][3]);
            acc[2][0] = ffma2(as2, w0, acc[2][0]); acc[2][1] = ffma2(as2, w1, acc[2][1]);
            acc[2][2] = ffma2(as2, w2, acc[2][2]); acc[2][3] = ffma2(as2, w3, acc[2][3]);
            acc[3][0] = ffma2(as3, w0, acc[3][0]); acc[3][1] = ffma2(as3, w1, acc[3][1]);
            acc[3][2] = ffma2(as3, w2, acc[3][2]); acc[3][3] = ffma2(as3, w3, acc[3][3]);
        }
        // no trailing sync: next iter's STS targets the other stage; the sync
        // inside the next iteration protects the overwrite two stages ahead.
    }
#pragma unroll
    for (int r = 0; r < 4; r++) {
        float2 v0 = unpack2(acc[r][0]), v1 = unpack2(acc[r][1]);
        float2 v2 = unpack2(acc[r][2]), v3 = unpack2(acc[r][3]);
        float* d = &part[(size_t)(rg + r) * G4 + col0 + cg];
        *(float4*)d = make_float4(v0.x, v0.y, v1.x, v1.y);
        *(float4*)(d + 4) = make_float4(v2.x, v2.y, v3.x, v3.y);
    }
    __syncthreads();   // protect smem reuse by an immediately-following tile_gemm call
}

// ---------------- LSTM pointwise (one h-element per thread) ----------------
static __device__ __forceinline__ void pointwise(
    const float* __restrict__ p1, int n1, const float* __restrict__ p2, int n2,
    const float* __restrict__ xadd,
    const float* __restrict__ bih, const float* __restrict__ bhh,
    float* __restrict__ c, float* __restrict__ hT1, float* __restrict__ hT2,
    float* __restrict__ hflat)
{
    int idx = blockIdx.x * TPB + threadIdx.x;  // 0..32767
    int b = idx >> 9, j = idx & 511;
    float g[4];
#pragma unroll
    for (int gi = 0; gi < 4; gi++) {
        int col = gi * 512 + j;
        size_t off = (size_t)b * G4 + col;
        float v = bih[col] + bhh[col];
        if (xadd) v += xadd[off];
        for (int s = 0; s < n1; s++) v += __ldcg(&p1[(size_t)s * PART + off]);
        for (int s = 0; s < n2; s++) v += __ldcg(&p2[(size_t)s * PART + off]);
        g[gi] = v;
    }
    float ig = sigmf(g[0]), fg = sigmf(g[1]), tg = tanhf(g[2]), og = sigmf(g[3]);
    float cn = fg * c[idx] + ig * tg;
    c[idx] = cn;
    float h = og * tanhf(cn);
    hT1[j * 64 + b] = h;
    if (hT2) hT2[j * 64 + b] = h;
    if (hflat) hflat[(size_t)b * 512 + j] = h;
}

// ---------------- attention (CTA = batch row b) ----------------
static __device__ __forceinline__ void attention(int b, float* hsh, float* ssh, float* ash) {
    int tid = threadIdx.x;
    for (int k = tid; k < 512; k += TPB) hsh[k] = __ldcg(&g_decA1T[(512 + k) * 64 + b]);
    __syncthreads();
    int w = tid >> 5, lane = tid & 31;
    for (int s = w; s < 64; s += 8) {
        const float* e = g_encouts + (size_t)s * 32768 + (size_t)b * 512;
        float d = 0.f;
#pragma unroll 4
        for (int k = lane; k < 512; k += 32) d += e[k] * hsh[k];
#pragma unroll
        for (int o = 16; o; o >>= 1) d += __shfl_down_sync(0xffffffffu, d, o);
        if (!lane) ssh[s] = d;
    }
    __syncthreads();
    if (tid < 32) {
        float s0 = ssh[tid], s1 = ssh[tid + 32];
        float m = fmaxf(s0, s1);
#pragma unroll
        for (int o = 16; o; o >>= 1) m = fmaxf(m, __shfl_xor_sync(0xffffffffu, m, o));
        float e0 = __expf(s0 - m), e1 = __expf(s1 - m);
        float sum = e0 + e1;
#pragma unroll
        for (int o = 16; o; o >>= 1) sum += __shfl_xor_sync(0xffffffffu, sum, o);
        float inv = 1.f / sum;
        ash[tid] = e0 * inv;
        ash[tid + 32] = e1 * inv;
    }
    __syncthreads();
    for (int j = tid; j < 512; j += TPB) {
        float acc = 0.f;
#pragma unroll 8
        for (int s = 0; s < 64; s++)
            acc += ash[s] * g_encouts[(size_t)s * 32768 + (size_t)b * 512 + j];
        g_decA0T[j * 64 + b] = acc;
    }
    __syncthreads();
}

// ---------------- persistent recurrence kernel ----------------
__global__ void __launch_bounds__(TPB, 1) recurrent(
    const float* __restrict__ ebih0, const float* __restrict__ ebhh0,
    const float* __restrict__ ebih1, const float* __restrict__ ebhh1,
    const float* __restrict__ dbih0, const float* __restrict__ dbhh0,
    const float* __restrict__ dbih1, const float* __restrict__ dbhh1)
{
    __shared__ __align__(16) float Ash[32][64];    // 2 stages
    __shared__ __align__(16) float Wsh[32][128];   // 2 stages
    __shared__ float hsh[512];
    __shared__ float ssh[64];
    __shared__ float ashm[64];
    const int bid = blockIdx.x;
    const int gid = bid * TPB + threadIdx.x;   // 0..32767

    // zero initial states (fresh each launch/replay)
    g_encA1T[gid] = 0.f;
    g_encA1T[gid + 32768] = 0.f;
    g_c0[gid] = 0.f;
    g_c1[gid] = 0.f;
    gbar();

    const int ks = bid >> 4;                   // 0..7
    const int colJ = (bid & 15) * 128;

    // prime: encoder L0 recurrent gemm for t=0 (zero state)
    tile_gemm(Ash, Wsh, g_encA1T, g_Wenc0T, ks * 64, 64, colJ, g_partB + (size_t)ks * PART);
    gbar();

    // ---- encoder: 2 phases per step ----
    for (int st = 0; st < SLEN; st++) {
        pointwise(g_partB, 8, nullptr, 0, g_Xenc + (size_t)st * PART, ebih0, ebhh0,
                  g_c0, g_encA1T, nullptr, nullptr);
        if (st > 0)
            pointwise(g_partA, 8, nullptr, 0, nullptr, ebih1, ebhh1,
                      g_c1, g_encA1T + 512 * 64, nullptr,
                      g_encouts + (size_t)(st - 1) * 32768);
        gbar();
        tile_gemm(Ash, Wsh, g_encA1T, g_Wenc1T, ks * 128, 128, colJ, g_partA + (size_t)ks * PART);
        if (st < SLEN - 1)
            tile_gemm(Ash, Wsh, g_encA1T, g_Wenc0T, ks * 64, 64, colJ, g_partB + (size_t)ks * PART);
        gbar();
    }
    // final pw1(63)
    pointwise(g_partA, 8, nullptr, 0, nullptr, ebih1, ebhh1,
              g_c1, g_encA1T + 512 * 64, nullptr, g_encouts + (size_t)(SLEN - 1) * 32768);
    gbar();

    // transition: encoder final states -> decoder layout
    {
        int j = gid >> 6, b = gid & 63;
        float h0 = __ldcg(&g_encA1T[j * 64 + b]);
        float h1 = __ldcg(&g_encA1T[(512 + j) * 64 + b]);
        g_decA0T[(512 + j) * 64 + b] = h0;
        g_decA1T[j * 64 + b] = h0;
        g_decA1T[(512 + j) * 64 + b] = h1;
    }
    gbar();

    for (int st = 0; st < DSTEPS; st++) {
        // phase A: attention (CTAs 0..63) || L0 gemm h0-half K=[512,1024) (CTAs 64..127)
        if (bid < 64) attention(bid, hsh, ssh, ashm);
        else tile_gemm(Ash, Wsh, g_decA0T, g_Wdec0T, ks * 128, 128, colJ,
                       g_partB + (size_t)ks * PART);
        gbar();
        // phase B: all CTAs, ctx-half K=[0,512)
        tile_gemm(Ash, Wsh, g_decA0T, g_Wdec0T, ks * 64, 64, colJ, g_partA + (size_t)ks * PART);
        gbar();
        // phase C: pointwise L0 (sum partA[0..7] + partB[4..7])
        pointwise(g_partA, 8, g_partB + 4 * (size_t)PART, 4,
                  g_Xdec + (size_t)st * PART, dbih0, dbhh0,
                  g_c0, g_decA0T + 512 * 64, g_decA1T, nullptr);
        gbar();
        // phase D: L1 gemm K=1024
        tile_gemm(Ash, Wsh, g_decA1T, g_Wdec1T, ks * 128, 128, colJ, g_partB + (size_t)ks * PART);
        gbar();
        // phase E: pointwise L1
        pointwise(g_partB, 8, nullptr, 0, nullptr, dbih1, dbhh1,
                  g_c1, g_decA1T + 512 * 64, nullptr, g_dech1 + (size_t)st * 32768);
        gbar();
    }
}

// ---------------- fused init: output-zero + embedding gather (one launch) ----------------
__global__ void init_gather(const int* __restrict__ src, const int* __restrict__ trg,
                            const float* __restrict__ enc_emb, const float* __restrict__ dec_emb,
                            float* __restrict__ out) {
    int blk = blockIdx.x;
    if (blk < 2032) {
        // 4 embedding rows per block (8128 rows total)
        int row = blk * 4 + (threadIdx.x >> 6);
        int t4 = threadIdx.x & 63;
        if (row < SLEN * BATCH) {
            int tok = src[row];
            reinterpret_cast<float4*>(g_embS + (size_t)row * EDIM)[t4] =
                reinterpret_cast<const float4*>(enc_emb + (size_t)tok * EDIM)[t4];
        } else {
            int r = row - SLEN * BATCH;
            int tok = trg[r];
            reinterpret_cast<float4*>(g_embT + (size_t)r * EDIM)[t4] =
                reinterpret_cast<const float4*>(dec_emb + (size_t)tok * EDIM)[t4];
        }
    } else {
        int i = (blk - 2032) * 256 + threadIdx.x;   // 1500 blocks * 256 = 384000
        if (i < BATCH * OUTV) out[i] = 0.0f;
    }
}

// fused 7-way transpose pack: dst[(dstk0+k)*2048 + r] = src[r*lds + coloff + k]
__global__ void transpose_all(
    const float* __restrict__ eWhh0, const float* __restrict__ eWih1, const float* __restrict__ eWhh1,
    const float* __restrict__ dWih0, const float* __restrict__ dWhh0,
    const float* __restrict__ dWih1, const float* __restrict__ dWhh1,
    float* __restrict__ W0T, float* __restrict__ W1T,
    float* __restrict__ D0T, float* __restrict__ D1T)
{
    __shared__ float tile[32][33];
    const float* src; int lds = 512, coloff = 0, dstk0 = 0; float* dst;
    switch (blockIdx.z) {
        case 0: src = eWhh0; dst = W0T; break;
        case 1: src = eWih1; dst = W1T; break;
        case 2: src = eWhh1; dst = W1T; dstk0 = 512; break;
        case 3: src = dWih0; dst = D0T; lds = 768; coloff = 256; break;
        case 4: src = dWhh0; dst = D0T; dstk0 = 512; break;
        case 5: src = dWih1; dst = D1T; break;
        default: src = dWhh1; dst = D1T; dstk0 = 512; break;
    }
    int rb = blockIdx.x * 32, kb = blockIdx.y * 32;
    int tx = threadIdx.x & 31, ty = threadIdx.x >> 5;
#pragma unroll
    for (int i = 0; i < 4; i++)
        tile[ty + i * 8][tx] = src[(size_t)(rb + ty + i * 8) * lds + coloff + kb + tx];
    __syncthreads();
#pragma unroll
    for (int i = 0; i < 4; i++)
        dst[(size_t)(dstk0 + kb + ty + i * 8) * 2048 + rb + tx] = tile[tx][ty + i * 8];
}

// ---------------- big GEMM core (f32x2, double-buffered smem) ----------------
static __device__ __forceinline__ void gemm_core(
    const float* __restrict__ A, int lda, const float* __restrict__ W, int ldw,
    const float* __restrict__ bias, float* __restrict__ C, int ldc,
    int M, int N, int K, int bx, int by)
{
    __shared__ __align__(16) float Ash[32][132];   // 2 stages of 16 k-rows
    __shared__ __align__(16) float Wsh[32][132];
    int row0 = by * 128, col0 = bx * 128;
    int tid = threadIdx.x;
    int tx = tid & 15, ty = tid >> 4;
    int lr = tid >> 2, lk4 = (tid & 3) * 4;
    u64 acc[4][8];
#pragma unroll
    for (int p = 0; p < 4; p++)
#pragma unroll
        for (int j = 0; j < 8; j++) acc[p][j] = 0ull;

    float4 avr[2], wvr[2];
#pragma unroll
    for (int h = 0; h < 2; h++) {
        int rr = lr + h * 64;
        int r = row0 + rr, c = col0 + rr;
        avr[h] = (r < M) ? *(const float4*)&A[(size_t)r * lda + lk4] : make_float4(0, 0, 0, 0);
        wvr[h] = (c < N) ? *(const float4*)&W[(size_t)c * ldw + lk4] : make_float4(0, 0, 0, 0);
    }
    const int nkb = K >> 4;
    for (int i = 0; i < nkb; i++) {
        const int s = (i & 1) << 4;
#pragma unroll
        for (int h = 0; h < 2; h++) {
            int rr = lr + h * 64;
            Ash[s + lk4 + 0][rr] = avr[h].x; Ash[s + lk4 + 1][rr] = avr[h].y;
            Ash[s + lk4 + 2][rr] = avr[h].z; Ash[s + lk4 + 3][rr] = avr[h].w;
            Wsh[s + lk4 + 0][rr] = wvr[h].x; Wsh[s + lk4 + 1][rr] = wvr[h].y;
            Wsh[s + lk4 + 2][rr] = wvr[h].z; Wsh[s + lk4 + 3][rr] = wvr[h].w;
        }
        __syncthreads();
        if (i + 1 < nkb) {
            int kn = (i + 1) * 16;
#pragma unroll
            for (int h = 0; h < 2; h++) {
                int rr = lr + h * 64;
                int r = row0 + rr, c = col0 + rr;
                avr[h] = (r < M) ? *(const float4*)&A[(size_t)r * lda + kn + lk4] : make_float4(0, 0, 0, 0);
                wvr[h] = (c < N) ? *(const float4*)&W[(size_t)c * ldw + kn + lk4] : make_float4(0, 0, 0, 0);
            }
        }
#pragma unroll
        for (int kk = 0; kk < 16; kk++) {
            const u64* ap = (const u64*)&Ash[s + kk][ty * 8];
            u64 a0 = ap[0], a1 = ap[1], a2 = ap[2], a3 = ap[3];
            float4 w0 = *(const float4*)&Wsh[s + kk][tx * 8];
            float4 w1 = *(const float4*)&Wsh[s + kk][tx * 8 + 4];
            u64 ws[8];
            ws[0] = splat2(w0.x); ws[1] = splat2(w0.y); ws[2] = splat2(w0.z); ws[3] = splat2(w0.w);
            ws[4] = splat2(w1.x); ws[5] = splat2(w1.y); ws[6] = splat2(w1.z); ws[7] = splat2(w1.w);
#pragma unroll
            for (int j = 0; j < 8; j++) {
                acc[0][j] = ffma2(a0, ws[j], acc[0][j]);
                acc[1][j] = ffma2(a1, ws[j], acc[1][j]);
                acc[2][j] = ffma2(a2, ws[j], acc[2][j]);
                acc[3][j] = ffma2(a3, ws[j], acc[3][j]);
            }
        }
        // no trailing sync (double-buffered)
    }
#pragma unroll
    for (int p = 0; p < 4; p++) {
        float2 v[8];
#pragma unroll
        for (int j = 0; j < 8; j++) v[j] = unpack2(acc[p][j]);
        int r = row0 + ty * 8 + p * 2;
        if (r < M) {
#pragma unroll
            for (int j = 0; j < 8; j++) {
                int c = col0 + tx * 8 + j;
                if (c < N) C[(size_t)r * ldc + c] = v[j].x + (bias ? bias[c] : 0.0f);
            }
        }
        if (r + 1 < M) {
#pragma unroll
            for (int j = 0; j < 8; j++) {
                int c = col0 + tx * 8 + j;
                if (c < N) C[(size_t)(r + 1) * ldc + c] = v[j].y + (bias ? bias[c] : 0.0f);
            }
        }
    }
}

__global__ void __launch_bounds__(256) big_gemm(
    const float* __restrict__ A, int lda, const float* __restrict__ W, int ldw,
    const float* __restrict__ bias, float* __restrict__ C, int ldc,
    int M, int N, int K)
{
    gemm_core(A, lda, W, ldw, bias, C, ldc, M, N, K, blockIdx.x, blockIdx.y);
}

// fused projection gemm: z=0 encoder, z=1 decoder
__global__ void __launch_bounds__(256) proj_gemm(
    const float* __restrict__ embS, const float* __restrict__ eWih0,
    const float* __restrict__ embT, const float* __restrict__ dWih0,
    float* __restrict__ Xenc, float* __restrict__ Xdec)
{
    if (blockIdx.z == 0)
        gemm_core(embS, EDIM, eWih0, EDIM, nullptr, Xenc, G4,
                  SLEN * BATCH, G4, EDIM, blockIdx.x, blockIdx.y);
    else
        gemm_core(embT, EDIM, dWih0, 768, nullptr, Xdec, G4,
                  DSTEPS * BATCH, G4, EDIM, blockIdx.x, blockIdx.y);
}

// ---------------- host ----------------
extern "C" void kernel_launch(void* const* d_in, const int* in_sizes, int n_in,
                              void* d_out, int out_size) {
    const int* src = (const int*)d_in[0];
    const int* trg = (const int*)d_in[1];
    const float* enc_emb = (const float*)d_in[2];
    const float* eWih0 = (const float*)d_in[3];
    const float* eWhh0 = (const float*)d_in[4];
    const float* ebih0 = (const float*)d_in[5];
    const float* ebhh0 = (const float*)d_in[6];
    const float* eWih1 = (const float*)d_in[7];
    const float* eWhh1 = (const float*)d_in[8];
    const float* ebih1 = (const float*)d_in[9];
    const float* ebhh1 = (const float*)d_in[10];
    const float* dec_emb = (const float*)d_in[11];
    const float* dWih0 = (const float*)d_in[12];
    const float* dWhh0 = (const float*)d_in[13];
    const float* dbih0 = (const float*)d_in[14];
    const float* dbhh0 = (const float*)d_in[15];
    const float* dWih1 = (const float*)d_in[16];
    const float* dWhh1 = (const float*)d_in[17];
    const float* dbih1 = (const float*)d_in[18];
    const float* dbhh1 = (const float*)d_in[19];
    const float* fcW = (const float*)d_in[20];
    const float* fcb = (const float*)d_in[21];
    float* out = (float*)d_out;

    float *Xenc, *Xdec, *embS, *embT, *dech1;
    float *W0T, *W1T, *D0T, *D1T;
    cudaGetSymbolAddress((void**)&Xenc, g_Xenc);
    cudaGetSymbolAddress((void**)&Xdec, g_Xdec);
    cudaGetSymbolAddress((void**)&embS, g_embS);
    cudaGetSymbolAddress((void**)&embT, g_embT);
    cudaGetSymbolAddress((void**)&dech1, g_dech1);
    cudaGetSymbolAddress((void**)&W0T, g_Wenc0T);
    cudaGetSymbolAddress((void**)&W1T, g_Wenc1T);
    cudaGetSymbolAddress((void**)&D0T, g_Wdec0T);
    cudaGetSymbolAddress((void**)&D1T, g_Wdec1T);

    // launch 1: fused zero + gather
    init_gather<<<2032 + 1500, 256>>>(src, trg, enc_emb, dec_emb, out);
    // launch 2: fused weight transposes
    transpose_all<<<dim3(64, 16, 7), 256>>>(eWhh0, eWih1, eWhh1, dWih0, dWhh0, dWih1, dWhh1,
                                            W0T, W1T, D0T, D1T);
    // launch 3: fused input projections
    proj_gemm<<<dim3(16, 32, 2), 256>>>(embS, eWih0, embT, dWih0, Xenc, Xdec);
    // launch 4: persistent recurrence  (now in the profiled slot)
    recurrent<<<NCTA, TPB>>>(ebih0, ebhh0, ebih1, ebhh1, dbih0, dbhh0, dbih1, dbhh1);
    // launch 5: final FC projection
    big_gemm<<<dim3(47, 32), 256>>>(dech1, 512, fcW, 512, fcb,
                                    out + (size_t)BATCH * OUTV, OUTV,
                                    DSTEPS * BATCH, OUTV, 512);
}

// round 13
// speedup vs baseline: 1.0431x; 1.0251x over previous
#include <cuda_runtime.h>
#include <cuda_bf16.h>

#define SLEN 64
#define BATCH 64
#define EDIM 256
#define G4 2048
#define OUTV 6000
#define DSTEPS 63
#define NCTA 128
#define TPB 256
#define PART (BATCH * G4)
#define FCM (DSTEPS * BATCH)   // 4032

typedef unsigned long long u64;
typedef unsigned int u32;
typedef unsigned short u16;

// ---------------- static device scratch ----------------
__device__ float g_Xenc[SLEN * PART];
__device__ float g_Xdec[DSTEPS * PART];
__device__ float g_embS[SLEN * BATCH * EDIM];
__device__ float g_embT[DSTEPS * BATCH * EDIM];
__device__ float g_encouts[SLEN * BATCH * 512];
__device__ float g_dech1[DSTEPS * BATCH * 512];
__device__ float g_partA[8 * PART];
__device__ float g_partB[8 * PART];
__device__ float g_Wenc0T[512 * 2048];
__device__ float g_Wenc1T[1024 * 2048];
__device__ float g_Wdec0T[1024 * 2048];
__device__ float g_Wdec1T[1024 * 2048];
__device__ float g_encA1T[1024 * 64];
__device__ float g_decA0T[1024 * 64];
__device__ float g_decA1T[1024 * 64];
__device__ float g_c0[BATCH * 512];
__device__ float g_c1[BATCH * 512];
__device__ unsigned g_bar_cnt;
__device__ unsigned g_bar_gen;
// split-bf16 FC operands
__device__ u16 g_Whi[OUTV * 512];
__device__ u16 g_Wlo[OUTV * 512];
__device__ u16 g_Ahi[FCM * 512];
__device__ u16 g_Alo[FCM * 512];

// ---------------- f32x2 helpers ----------------
static __device__ __forceinline__ u64 splat2(float x) {
    u64 r; asm("mov.b64 %0, {%1, %1};" : "=l"(r) : "f"(x)); return r;
}
static __device__ __forceinline__ u64 ffma2(u64 a, u64 b, u64 c) {
    u64 d; asm("fma.rn.f32x2 %0, %1, %2, %3;" : "=l"(d) : "l"(a), "l"(b), "l"(c)); return d;
}
static __device__ __forceinline__ float2 unpack2(u64 v) {
    float2 r; asm("mov.b64 {%0, %1}, %2;" : "=f"(r.x), "=f"(r.y) : "l"(v)); return r;
}
static __device__ __forceinline__ float sigmf(float x) {
    return 1.0f / (1.0f + __expf(-x));
}

// ---------------- grid barrier (atomic acq/rel — best measured) ----------------
static __device__ __forceinline__ void gbar() {
    __syncthreads();
    if (threadIdx.x == 0) {
        unsigned gen;
        asm volatile("ld.acquire.gpu.u32 %0, [%1];" : "=r"(gen) : "l"(&g_bar_gen) : "memory");
        unsigned prev;
        asm volatile("atom.acq_rel.gpu.add.u32 %0, [%1], %2;"
                     : "=r"(prev) : "l"(&g_bar_cnt), "r"(1u) : "memory");
        if (prev == NCTA - 1) {
            asm volatile("st.relaxed.gpu.u32 [%0], %1;" :: "l"(&g_bar_cnt), "r"(0u) : "memory");
            asm volatile("st.release.gpu.u32 [%0], %1;" :: "l"(&g_bar_gen), "r"(gen + 1u) : "memory");
        } else {
            unsigned cur;
            do {
                asm volatile("ld.acquire.gpu.u32 %0, [%1];" : "=r"(cur) : "l"(&g_bar_gen) : "memory");
            } while (cur == gen);
        }
    }
    __syncthreads();
}

// ---------------- tile GEMM: 64 rows x 128 cols (R10 single-buffer) ----------------
static __device__ __forceinline__ void tile_gemm(
    float (*Ash)[64], float (*Wsh)[128],
    const float* __restrict__ AT, const float* __restrict__ WT,
    int k0, int klen, int col0, float* __restrict__ part)
{
    const int t = threadIdx.x;
    const int rg = (t & 15) * 4;
    const int cg = (t >> 4) * 8;
    u64 acc[4][4];
#pragma unroll
    for (int r = 0; r < 4; r++)
#pragma unroll
        for (int c = 0; c < 4; c++) acc[r][c] = 0ull;

    const int ka = t >> 4, ca = (t & 15) * 4;
    const int kw0 = t >> 5, cw0 = (t & 31) * 4;
    const int kw1 = (t + 256) >> 5, cw1 = ((t + 256) & 31) * 4;
    float4 av, wv0, wv1;
    av  = __ldcg((const float4*)&AT[(size_t)(k0 + ka) * 64 + ca]);
    wv0 = *(const float4*)&WT[(size_t)(k0 + kw0) * 2048 + col0 + cw0];
    wv1 = *(const float4*)&WT[(size_t)(k0 + kw1) * 2048 + col0 + cw1];

    for (int kb = 0; kb < klen; kb += 16) {
        *(float4*)&Ash[ka][ca] = av;
        *(float4*)&Wsh[kw0][cw0] = wv0;
        *(float4*)&Wsh[kw1][cw1] = wv1;
        __syncthreads();
        if (kb + 16 < klen) {
            int kn = k0 + kb + 16;
            av  = __ldcg((const float4*)&AT[(size_t)(kn + ka) * 64 + ca]);
            wv0 = *(const float4*)&WT[(size_t)(kn + kw0) * 2048 + col0 + cw0];
            wv1 = *(const float4*)&WT[(size_t)(kn + kw1) * 2048 + col0 + cw1];
        }
#pragma unroll
        for (int kk = 0; kk < 16; kk++) {
            float4 a4 = *(const float4*)&Ash[kk][rg];
            u64 as0 = splat2(a4.x), as1 = splat2(a4.y), as2 = splat2(a4.z), as3 = splat2(a4.w);
            const u64* wd = (const u64*)&Wsh[kk][cg];
            u64 w0 = wd[0], w1 = wd[1], w2 = wd[2], w3 = wd[3];
            acc[0][0] = ffma2(as0, w0, acc[0][0]); acc[0][1] = ffma2(as0, w1, acc[0][1]);
            acc[0][2] = ffma2(as0, w2, acc[0][2]); acc[0][3] = ffma2(as0, w3, acc[0][3]);
            acc[1][0] = ffma2(as1, w0, acc[1][0]); acc[1][1] = ffma2(as1, w1, acc[1][1]);
            acc[1][2] = ffma2(as1, w2, acc[1][2]); acc[1][3] = ffma2(as1, w3, acc[1][3]);
            acc[2][0] = ffma2(as2, w0, acc[2][0]); acc[2][1] = ffma2(as2, w1, acc[2][1]);
            acc[2][2] = ffma2(as2, w2, acc[2][2]); acc[2][3] = ffma2(as2, w3, acc[2][3]);
            acc[3][0] = ffma2(as3, w0, acc[3][0]); acc[3][1] = ffma2(as3, w1, acc[3][1]);
            acc[3][2] = ffma2(as3, w2, acc[3][2]); acc[3][3] = ffma2(as3, w3, acc[3][3]);
        }
        __syncthreads();
    }
#pragma unroll
    for (int r = 0; r < 4; r++) {
        float2 v0 = unpack2(acc[r][0]), v1 = unpack2(acc[r][1]);
        float2 v2 = unpack2(acc[r][2]), v3 = unpack2(acc[r][3]);
        float* d = &part[(size_t)(rg + r) * G4 + col0 + cg];
        *(float4*)d = make_float4(v0.x, v0.y, v1.x, v1.y);
        *(float4*)(d + 4) = make_float4(v2.x, v2.y, v3.x, v3.y);
    }
}

// ---------------- LSTM pointwise ----------------
static __device__ __forceinline__ void pointwise(
    const float* __restrict__ p1, int n1, const float* __restrict__ p2, int n2,
    const float* __restrict__ xadd,
    const float* __restrict__ bih, const float* __restrict__ bhh,
    float* __restrict__ c, float* __restrict__ hT1, float* __restrict__ hT2,
    float* __restrict__ hflat)
{
    int idx = blockIdx.x * TPB + threadIdx.x;
    int b = idx >> 9, j = idx & 511;
    float g[4];
#pragma unroll
    for (int gi = 0; gi < 4; gi++) {
        int col = gi * 512 + j;
        size_t off = (size_t)b * G4 + col;
        float v = bih[col] + bhh[col];
        if (xadd) v += xadd[off];
        for (int s = 0; s < n1; s++) v += __ldcg(&p1[(size_t)s * PART + off]);
        for (int s = 0; s < n2; s++) v += __ldcg(&p2[(size_t)s * PART + off]);
        g[gi] = v;
    }
    float ig = sigmf(g[0]), fg = sigmf(g[1]), tg = tanhf(g[2]), og = sigmf(g[3]);
    float cn = fg * c[idx] + ig * tg;
    c[idx] = cn;
    float h = og * tanhf(cn);
    hT1[j * 64 + b] = h;
    if (hT2) hT2[j * 64 + b] = h;
    if (hflat) hflat[(size_t)b * 512 + j] = h;
}

// ---------------- attention (CTA = batch row b) ----------------
static __device__ __forceinline__ void attention(int b, float* hsh, float* ssh, float* ash) {
    int tid = threadIdx.x;
    for (int k = tid; k < 512; k += TPB) hsh[k] = __ldcg(&g_decA1T[(512 + k) * 64 + b]);
    __syncthreads();
    int w = tid >> 5, lane = tid & 31;
    for (int s = w; s < 64; s += 8) {
        const float* e = g_encouts + (size_t)s * 32768 + (size_t)b * 512;
        float d = 0.f;
#pragma unroll 4
        for (int k = lane; k < 512; k += 32) d += e[k] * hsh[k];
#pragma unroll
        for (int o = 16; o; o >>= 1) d += __shfl_down_sync(0xffffffffu, d, o);
        if (!lane) ssh[s] = d;
    }
    __syncthreads();
    if (tid < 32) {
        float s0 = ssh[tid], s1 = ssh[tid + 32];
        float m = fmaxf(s0, s1);
#pragma unroll
        for (int o = 16; o; o >>= 1) m = fmaxf(m, __shfl_xor_sync(0xffffffffu, m, o));
        float e0 = __expf(s0 - m), e1 = __expf(s1 - m);
        float sum = e0 + e1;
#pragma unroll
        for (int o = 16; o; o >>= 1) sum += __shfl_xor_sync(0xffffffffu, sum, o);
        float inv = 1.f / sum;
        ash[tid] = e0 * inv;
        ash[tid + 32] = e1 * inv;
    }
    __syncthreads();
    for (int j = tid; j < 512; j += TPB) {
        float acc = 0.f;
#pragma unroll 8
        for (int s = 0; s < 64; s++)
            acc += ash[s] * g_encouts[(size_t)s * 32768 + (size_t)b * 512 + j];
        g_decA0T[j * 64 + b] = acc;
    }
    __syncthreads();
}

// ---------------- persistent recurrence kernel ----------------
__global__ void __launch_bounds__(TPB, 1) recurrent(
    const float* __restrict__ ebih0, const float* __restrict__ ebhh0,
    const float* __restrict__ ebih1, const float* __restrict__ ebhh1,
    const float* __restrict__ dbih0, const float* __restrict__ dbhh0,
    const float* __restrict__ dbih1, const float* __restrict__ dbhh1)
{
    __shared__ __align__(16) float Ash[16][64];
    __shared__ __align__(16) float Wsh[16][128];
    __shared__ float hsh[512];
    __shared__ float ssh[64];
    __shared__ float ashm[64];
    const int bid = blockIdx.x;
    const int gid = bid * TPB + threadIdx.x;

    g_encA1T[gid] = 0.f;
    g_encA1T[gid + 32768] = 0.f;
    g_c0[gid] = 0.f;
    g_c1[gid] = 0.f;
    gbar();

    const int ks = bid >> 4;
    const int colJ = (bid & 15) * 128;

    tile_gemm(Ash, Wsh, g_encA1T, g_Wenc0T, ks * 64, 64, colJ, g_partB + (size_t)ks * PART);
    gbar();

    // ---- encoder: 2 phases per step ----
    for (int st = 0; st < SLEN; st++) {
        pointwise(g_partB, 8, nullptr, 0, g_Xenc + (size_t)st * PART, ebih0, ebhh0,
                  g_c0, g_encA1T, nullptr, nullptr);
        if (st > 0)
            pointwise(g_partA, 8, nullptr, 0, nullptr, ebih1, ebhh1,
                      g_c1, g_encA1T + 512 * 64, nullptr,
                      g_encouts + (size_t)(st - 1) * 32768);
        gbar();
        tile_gemm(Ash, Wsh, g_encA1T, g_Wenc1T, ks * 128, 128, colJ, g_partA + (size_t)ks * PART);
        if (st < SLEN - 1)
            tile_gemm(Ash, Wsh, g_encA1T, g_Wenc0T, ks * 64, 64, colJ, g_partB + (size_t)ks * PART);
        gbar();
    }
    pointwise(g_partA, 8, nullptr, 0, nullptr, ebih1, ebhh1,
              g_c1, g_encA1T + 512 * 64, nullptr, g_encouts + (size_t)(SLEN - 1) * 32768);
    gbar();

    // transition
    {
        int j = gid >> 6, b = gid & 63;
        float h0 = __ldcg(&g_encA1T[j * 64 + b]);
        float h1 = __ldcg(&g_encA1T[(512 + j) * 64 + b]);
        g_decA0T[(512 + j) * 64 + b] = h0;
        g_decA1T[j * 64 + b] = h0;
        g_decA1T[(512 + j) * 64 + b] = h1;
    }
    gbar();

    // ---- decoder: x=0 rebalanced schedule ----
    for (int st = 0; st < DSTEPS; st++) {
        // phase A: attention only (CTAs 0..63)
        if (bid < 64) attention(bid, hsh, ssh, ashm);
        gbar();
        // phase B: FULL L0 gemm K=1024, all 128 CTAs (K=128 each)
        tile_gemm(Ash, Wsh, g_decA0T, g_Wdec0T, ks * 128, 128, colJ, g_partA + (size_t)ks * PART);
        gbar();
        // phase C: pointwise L0
        pointwise(g_partA, 8, nullptr, 0,
                  g_Xdec + (size_t)st * PART, dbih0, dbhh0,
                  g_c0, g_decA0T + 512 * 64, g_decA1T, nullptr);
        gbar();
        // phase D: FULL L1 gemm K=1024
        tile_gemm(Ash, Wsh, g_decA1T, g_Wdec1T, ks * 128, 128, colJ, g_partB + (size_t)ks * PART);
        gbar();
        // phase E: pointwise L1
        pointwise(g_partB, 8, nullptr, 0, nullptr, dbih1, dbhh1,
                  g_c1, g_decA1T + 512 * 64, nullptr, g_dech1 + (size_t)st * 32768);
        gbar();
    }
}

// ---------------- fused init: output-zero + embedding gather ----------------
__global__ void init_gather(const int* __restrict__ src, const int* __restrict__ trg,
                            const float* __restrict__ enc_emb, const float* __restrict__ dec_emb,
                            float* __restrict__ out) {
    int blk = blockIdx.x;
    if (blk < 2032) {
        int row = blk * 4 + (threadIdx.x >> 6);
        int t4 = threadIdx.x & 63;
        if (row < SLEN * BATCH) {
            int tok = src[row];
            reinterpret_cast<float4*>(g_embS + (size_t)row * EDIM)[t4] =
                reinterpret_cast<const float4*>(enc_emb + (size_t)tok * EDIM)[t4];
        } else {
            int r = row - SLEN * BATCH;
            int tok = trg[r];
            reinterpret_cast<float4*>(g_embT + (size_t)r * EDIM)[t4] =
                reinterpret_cast<const float4*>(dec_emb + (size_t)tok * EDIM)[t4];
        }
    } else {
        int i = (blk - 2032) * 256 + threadIdx.x;
        if (i < BATCH * OUTV) out[i] = 0.0f;
    }
}

// ---------------- transpose pack ----------------
__global__ void transpose_all(
    const float* __restrict__ eWhh0, const float* __restrict__ eWih1, const float* __restrict__ eWhh1,
    const float* __restrict__ dWih0, const float* __restrict__ dWhh0,
    const float* __restrict__ dWih1, const float* __restrict__ dWhh1,
    float* __restrict__ W0T, float* __restrict__ W1T,
    float* __restrict__ D0T, float* __restrict__ D1T)
{
    __shared__ float tile[32][33];
    const float* src; int lds = 512, coloff = 0, dstk0 = 0; float* dst;
    switch (blockIdx.z) {
        case 0: src = eWhh0; dst = W0T; break;
        case 1: src = eWih1; dst = W1T; break;
        case 2: src = eWhh1; dst = W1T; dstk0 = 512; break;
        case 3: src = dWih0; dst = D0T; lds = 768; coloff = 256; break;
        case 4: src = dWhh0; dst = D0T; dstk0 = 512; break;
        case 5: src = dWih1; dst = D1T; break;
        default: src = dWhh1; dst = D1T; dstk0 = 512; break;
    }
    int rb = blockIdx.x * 32, kb = blockIdx.y * 32;
    int tx = threadIdx.x & 31, ty = threadIdx.x >> 5;
#pragma unroll
    for (int i = 0; i < 4; i++)
        tile[ty + i * 8][tx] = src[(size_t)(rb + ty + i * 8) * lds + coloff + kb + tx];
    __syncthreads();
#pragma unroll
    for (int i = 0; i < 4; i++)
        dst[(size_t)(dstk0 + kb + ty + i * 8) * 2048 + rb + tx] = tile[tx][ty + i * 8];
}

// ---------------- big GEMM core (R10 f32x2, used by proj) ----------------
static __device__ __forceinline__ void gemm_core(
    const float* __restrict__ A, int lda, const float* __restrict__ W, int ldw,
    const float* __restrict__ bias, float* __restrict__ C, int ldc,
    int M, int N, int K, int bx, int by)
{
    __shared__ __align__(16) float Ash[16][132];
    __shared__ __align__(16) float Wsh[16][132];
    int row0 = by * 128, col0 = bx * 128;
    int tid = threadIdx.x;
    int tx = tid & 15, ty = tid >> 4;
    int lr = tid >> 2, lk4 = (tid & 3) * 4;
    u64 acc[4][8];
#pragma unroll
    for (int p = 0; p < 4; p++)
#pragma unroll
        for (int j = 0; j < 8; j++) acc[p][j] = 0ull;

    float4 avr[2], wvr[2];
#pragma unroll
    for (int h = 0; h < 2; h++) {
        int rr = lr + h * 64;
        int r = row0 + rr, c = col0 + rr;
        avr[h] = (r < M) ? *(const float4*)&A[(size_t)r * lda + lk4] : make_float4(0, 0, 0, 0);
        wvr[h] = (c < N) ? *(const float4*)&W[(size_t)c * ldw + lk4] : make_float4(0, 0, 0, 0);
    }
    for (int kb = 0; kb < K; kb += 16) {
#pragma unroll
        for (int h = 0; h < 2; h++) {
            int rr = lr + h * 64;
            Ash[lk4 + 0][rr] = avr[h].x; Ash[lk4 + 1][rr] = avr[h].y;
            Ash[lk4 + 2][rr] = avr[h].z; Ash[lk4 + 3][rr] = avr[h].w;
            Wsh[lk4 + 0][rr] = wvr[h].x; Wsh[lk4 + 1][rr] = wvr[h].y;
            Wsh[lk4 + 2][rr] = wvr[h].z; Wsh[lk4 + 3][rr] = wvr[h].w;
        }
        __syncthreads();
        if (kb + 16 < K) {
            int kn = kb + 16;
#pragma unroll
            for (int h = 0; h < 2; h++) {
                int rr = lr + h * 64;
                int r = row0 + rr, c = col0 + rr;
                avr[h] = (r < M) ? *(const float4*)&A[(size_t)r * lda + kn + lk4] : make_float4(0, 0, 0, 0);
                wvr[h] = (c < N) ? *(const float4*)&W[(size_t)c * ldw + kn + lk4] : make_float4(0, 0, 0, 0);
            }
        }
#pragma unroll
        for (int kk = 0; kk < 16; kk++) {
            const u64* ap = (const u64*)&Ash[kk][ty * 8];
            u64 a0 = ap[0], a1 = ap[1], a2 = ap[2], a3 = ap[3];
            float4 w0 = *(const float4*)&Wsh[kk][tx * 8];
            float4 w1 = *(const float4*)&Wsh[kk][tx * 8 + 4];
            u64 ws[8];
            ws[0] = splat2(w0.x); ws[1] = splat2(w0.y); ws[2] = splat2(w0.z); ws[3] = splat2(w0.w);
            ws[4] = splat2(w1.x); ws[5] = splat2(w1.y); ws[6] = splat2(w1.z); ws[7] = splat2(w1.w);
#pragma unroll
            for (int j = 0; j < 8; j++) {
                acc[0][j] = ffma2(a0, ws[j], acc[0][j]);
                acc[1][j] = ffma2(a1, ws[j], acc[1][j]);
                acc[2][j] = ffma2(a2, ws[j], acc[2][j]);
                acc[3][j] = ffma2(a3, ws[j], acc[3][j]);
            }
        }
        __syncthreads();
    }
#pragma unroll
    for (int p = 0; p < 4; p++) {
        float2 v[8];
#pragma unroll
        for (int j = 0; j < 8; j++) v[j] = unpack2(acc[p][j]);
        int r = row0 + ty * 8 + p * 2;
        if (r < M) {
#pragma unroll
            for (int j = 0; j < 8; j++) {
                int c = col0 + tx * 8 + j;
                if (c < N) C[(size_t)r * ldc + c] = v[j].x + (bias ? bias[c] : 0.0f);
            }
        }
        if (r + 1 < M) {
#pragma unroll
            for (int j = 0; j < 8; j++) {
                int c = col0 + tx * 8 + j;
                if (c < N) C[(size_t)(r + 1) * ldc + c] = v[j].y + (bias ? bias[c] : 0.0f);
            }
        }
    }
}

__global__ void __launch_bounds__(256) proj_gemm(
    const float* __restrict__ embS, const float* __restrict__ eWih0,
    const float* __restrict__ embT, const float* __restrict__ dWih0,
    float* __restrict__ Xenc, float* __restrict__ Xdec)
{
    if (blockIdx.z == 0)
        gemm_core(embS, EDIM, eWih0, EDIM, nullptr, Xenc, G4,
                  SLEN * BATCH, G4, EDIM, blockIdx.x, blockIdx.y);
    else
        gemm_core(embT, EDIM, dWih0, 768, nullptr, Xdec, G4,
                  DSTEPS * BATCH, G4, EDIM, blockIdx.x, blockIdx.y);
}

// ---------------- split fp32 -> bf16 hi/lo (W and dech1) ----------------
__global__ void split_bf16(const float* __restrict__ fcW) {
    int i = blockIdx.x * 256 + threadIdx.x;
    if (i < OUTV * 512) {
        float x = fcW[i];
        __nv_bfloat16 h = __float2bfloat16(x);
        __nv_bfloat16 l = __float2bfloat16(x - __bfloat162float(h));
        g_Whi[i] = *(u16*)&h;
        g_Wlo[i] = *(u16*)&l;
    }
    if (i < FCM * 512) {
        float x = g_dech1[i];
        __nv_bfloat16 h = __float2bfloat16(x);
        __nv_bfloat16 l = __float2bfloat16(x - __bfloat162float(h));
        g_Ahi[i] = *(u16*)&h;
        g_Alo[i] = *(u16*)&l;
    }
}

// ---------------- FC via split-bf16 mma.sync (m16n8k16) ----------------
static __device__ __forceinline__ void mma16816(float* d, const u32* a, const u32* b) {
    asm volatile(
        "mma.sync.aligned.m16n8k16.row.col.f32.bf16.bf16.f32 "
        "{%0,%1,%2,%3}, {%4,%5,%6,%7}, {%8,%9}, {%0,%1,%2,%3};\n"
        : "+f"(d[0]), "+f"(d[1]), "+f"(d[2]), "+f"(d[3])
        : "r"(a[0]), "r"(a[1]), "r"(a[2]), "r"(a[3]), "r"(b[0]), "r"(b[1]));
}

__global__ void __launch_bounds__(256) fc_hmma(const float* __restrict__ bias,
                                               float* __restrict__ out) {
    __shared__ __align__(16) u16 sA[2][128][16];   // [hi/lo][row][k]
    __shared__ __align__(16) u16 sW[2][128][16];   // [hi/lo][col][k]
    const int m0 = blockIdx.y * 128, n0 = blockIdx.x * 128;
    const int tid = threadIdx.x;
    const int w = tid >> 5, lane = tid & 31;
    const int wr = (w & 3) * 32;   // warp row base in tile
    const int wc = (w >> 2) * 64;  // warp col base in tile
    const int lg = lane >> 2, lk = (lane & 3) * 2;

    float acc[2][8][4];
#pragma unroll
    for (int mt = 0; mt < 2; mt++)
#pragma unroll
        for (int nt = 0; nt < 8; nt++)
#pragma unroll
            for (int q = 0; q < 4; q++) acc[mt][nt][q] = 0.f;

    const int lrow = tid >> 1, lhalf = (tid & 1) * 8;
    for (int kc = 0; kc < 512; kc += 16) {
        // stage tiles (float4 = 8 bf16)
        {
            int gr = m0 + lrow;
            float4 ah = make_float4(0, 0, 0, 0), al = ah;
            if (gr < FCM) {
                ah = *(const float4*)&g_Ahi[(size_t)gr * 512 + kc + lhalf];
                al = *(const float4*)&g_Alo[(size_t)gr * 512 + kc + lhalf];
            }
            *(float4*)&sA[0][lrow][lhalf] = ah;
            *(float4*)&sA[1][lrow][lhalf] = al;
            int gc = n0 + lrow;
            float4 wh = make_float4(0, 0, 0, 0), wl = wh;
            if (gc < OUTV) {
                wh = *(const float4*)&g_Whi[(size_t)gc * 512 + kc + lhalf];
                wl = *(const float4*)&g_Wlo[(size_t)gc * 512 + kc + lhalf];
            }
            *(float4*)&sW[0][lrow][lhalf] = wh;
            *(float4*)&sW[1][lrow][lhalf] = wl;
        }
        __syncthreads();
        // load fragments
        u32 af[2][2][4], bf[2][8][2];
#pragma unroll
        for (int s = 0; s < 2; s++)
#pragma unroll
            for (int mt = 0; mt < 2; mt++) {
                int r0 = wr + mt * 16 + lg;
                af[s][mt][0] = *(const u32*)&sA[s][r0][lk];
                af[s][mt][1] = *(const u32*)&sA[s][r0 + 8][lk];
                af[s][mt][2] = *(const u32*)&sA[s][r0][lk + 8];
                af[s][mt][3] = *(const u32*)&sA[s][r0 + 8][lk + 8];
            }
#pragma unroll
        for (int s = 0; s < 2; s++)
#pragma unroll
            for (int nt = 0; nt < 8; nt++) {
                int c0 = wc + nt * 8 + lg;
                bf[s][nt][0] = *(const u32*)&sW[s][c0][lk];
                bf[s][nt][1] = *(const u32*)&sW[s][c0][lk + 8];
            }
#pragma unroll
        for (int mt = 0; mt < 2; mt++)
#pragma unroll
            for (int nt = 0; nt < 8; nt++) {
                mma16816(acc[mt][nt], af[0][mt], bf[0][nt]);  // hi*hi
                mma16816(acc[mt][nt], af[0][mt], bf[1][nt]);  // hi*lo
                mma16816(acc[mt][nt], af[1][mt], bf[0][nt]);  // lo*hi
            }
        __syncthreads();
    }
    // store with bias
#pragma unroll
    for (int mt = 0; mt < 2; mt++)
#pragma unroll
        for (int nt = 0; nt < 8; nt++) {
            int r = m0 + wr + mt * 16 + lg;
            int c = n0 + wc + nt * 8 + lk;
            float* d = acc[mt][nt];
            if (r < FCM) {
                if (c < OUTV)     out[(size_t)r * OUTV + c]     = d[0] + bias[c];
                if (c + 1 < OUTV) out[(size_t)r * OUTV + c + 1] = d[1] + bias[c + 1];
            }
            if (r + 8 < FCM) {
                if (c < OUTV)     out[(size_t)(r + 8) * OUTV + c]     = d[2] + bias[c];
                if (c + 1 < OUTV) out[(size_t)(r + 8) * OUTV + c + 1] = d[3] + bias[c + 1];
            }
        }
}

// ---------------- host ----------------
extern "C" void kernel_launch(void* const* d_in, const int* in_sizes, int n_in,
                              void* d_out, int out_size) {
    const int* src = (const int*)d_in[0];
    const int* trg = (const int*)d_in[1];
    const float* enc_emb = (const float*)d_in[2];
    const float* eWih0 = (const float*)d_in[3];
    const float* eWhh0 = (const float*)d_in[4];
    const float* ebih0 = (const float*)d_in[5];
    const float* ebhh0 = (const float*)d_in[6];
    const float* eWih1 = (const float*)d_in[7];
    const float* eWhh1 = (const float*)d_in[8];
    const float* ebih1 = (const float*)d_in[9];
    const float* ebhh1 = (const float*)d_in[10];
    const float* dec_emb = (const float*)d_in[11];
    const float* dWih0 = (const float*)d_in[12];
    const float* dWhh0 = (const float*)d_in[13];
    const float* dbih0 = (const float*)d_in[14];
    const float* dbhh0 = (const float*)d_in[15];
    const float* dWih1 = (const float*)d_in[16];
    const float* dWhh1 = (const float*)d_in[17];
    const float* dbih1 = (const float*)d_in[18];
    const float* dbhh1 = (const float*)d_in[19];
    const float* fcW = (const float*)d_in[20];
    const float* fcb = (const float*)d_in[21];
    float* out = (float*)d_out;

    float *Xenc, *Xdec, *embS, *embT;
    float *W0T, *W1T, *D0T, *D1T;
    cudaGetSymbolAddress((void**)&Xenc, g_Xenc);
    cudaGetSymbolAddress((void**)&Xdec, g_Xdec);
    cudaGetSymbolAddress((void**)&embS, g_embS);
    cudaGetSymbolAddress((void**)&embT, g_embT);
    cudaGetSymbolAddress((void**)&W0T, g_Wenc0T);
    cudaGetSymbolAddress((void**)&W1T, g_Wenc1T);
    cudaGetSymbolAddress((void**)&D0T, g_Wdec0T);
    cudaGetSymbolAddress((void**)&D1T, g_Wdec1T);

    // 1: fused zero + gather
    init_gather<<<2032 + 1500, 256>>>(src, trg, enc_emb, dec_emb, out);
    // 2: weight transposes
    transpose_all<<<dim3(64, 16, 7), 256>>>(eWhh0, eWih1, eWhh1, dWih0, dWhh0, dWih1, dWhh1,
                                            W0T, W1T, D0T, D1T);
    // 3: input projections
    proj_gemm<<<dim3(16, 32, 2), 256>>>(embS, eWih0, embT, dWih0, Xenc, Xdec);
    // 4: persistent recurrence (profiled slot)
    recurrent<<<NCTA, TPB>>>(ebih0, ebhh0, ebih1, ebhh1, dbih0, dbhh0, dbih1, dbhh1);
    // 5: split W and dech1 into bf16 hi/lo
    split_bf16<<<(OUTV * 512 + 255) / 256, 256>>>(fcW);
    // 6: tensor-core FC
    fc_hmma<<<dim3(47, 32), 256>>>(fcb, out + (size_t)BATCH * OUTV);
}

// round 15
// speedup vs baseline: 1.0506x; 1.0071x over previous
#include <cuda_runtime.h>
#include <cuda_bf16.h>

#define SLEN 64
#define BATCH 64
#define EDIM 256
#define G4 2048
#define OUTV 6000
#define DSTEPS 63
#define NCTA 128
#define TPB 256
#define PART (BATCH * G4)
#define FCM (DSTEPS * BATCH)   // 4032

typedef unsigned long long u64;
typedef unsigned int u32;
typedef unsigned short u16;

// ---------------- static device scratch ----------------
__device__ float g_Xenc[SLEN * PART];
__device__ float g_Xdec[DSTEPS * PART];
__device__ float g_embS[SLEN * BATCH * EDIM];
__device__ float g_embT[DSTEPS * BATCH * EDIM];
__device__ float g_encouts[SLEN * BATCH * 512];
__device__ float g_partA[8 * PART];
__device__ float g_partB[8 * PART];
__device__ float g_Wenc0T[512 * 2048];
__device__ float g_Wenc1T[1024 * 2048];
__device__ float g_Wdec0T[1024 * 2048];
__device__ float g_Wdec1T[1024 * 2048];
__device__ float g_encA1T[1024 * 64];
__device__ float g_decA0T[1024 * 64];
__device__ float g_decA1T[1024 * 64];
__device__ float g_c0[BATCH * 512];
__device__ float g_c1[BATCH * 512];
__device__ unsigned g_bar_cnt;
__device__ unsigned g_bar_gen;
// split-bf16 FC operands
__device__ u16 g_Whi[OUTV * 512];
__device__ u16 g_Wlo[OUTV * 512];
__device__ u16 g_Ahi[FCM * 512];
__device__ u16 g_Alo[FCM * 512];

// ---------------- f32x2 helpers ----------------
static __device__ __forceinline__ u64 splat2(float x) {
    u64 r; asm("mov.b64 %0, {%1, %1};" : "=l"(r) : "f"(x)); return r;
}
static __device__ __forceinline__ u64 ffma2(u64 a, u64 b, u64 c) {
    u64 d; asm("fma.rn.f32x2 %0, %1, %2, %3;" : "=l"(d) : "l"(a), "l"(b), "l"(c)); return d;
}
static __device__ __forceinline__ float2 unpack2(u64 v) {
    float2 r; asm("mov.b64 {%0, %1}, %2;" : "=f"(r.x), "=f"(r.y) : "l"(v)); return r;
}
static __device__ __forceinline__ float sigmf(float x) {
    return 1.0f / (1.0f + __expf(-x));
}

// ---------------- grid barrier (atomic acq/rel) ----------------
static __device__ __forceinline__ void gbar() {
    __syncthreads();
    if (threadIdx.x == 0) {
        unsigned gen;
        asm volatile("ld.acquire.gpu.u32 %0, [%1];" : "=r"(gen) : "l"(&g_bar_gen) : "memory");
        unsigned prev;
        asm volatile("atom.acq_rel.gpu.add.u32 %0, [%1], %2;"
                     : "=r"(prev) : "l"(&g_bar_cnt), "r"(1u) : "memory");
        if (prev == NCTA - 1) {
            asm volatile("st.relaxed.gpu.u32 [%0], %1;" :: "l"(&g_bar_cnt), "r"(0u) : "memory");
            asm volatile("st.release.gpu.u32 [%0], %1;" :: "l"(&g_bar_gen), "r"(gen + 1u) : "memory");
        } else {
            unsigned cur;
            do {
                asm volatile("ld.acquire.gpu.u32 %0, [%1];" : "=r"(cur) : "l"(&g_bar_gen) : "memory");
            } while (cur == gen);
        }
    }
    __syncthreads();
}

// ---------------- tile GEMM: 64 rows x 128 cols (R10 single-buffer) ----------------
static __device__ __forceinline__ void tile_gemm(
    float (*Ash)[64], float (*Wsh)[128],
    const float* __restrict__ AT, const float* __restrict__ WT,
    int k0, int klen, int col0, float* __restrict__ part)
{
    const int t = threadIdx.x;
    const int rg = (t & 15) * 4;
    const int cg = (t >> 4) * 8;
    u64 acc[4][4];
#pragma unroll
    for (int r = 0; r < 4; r++)
#pragma unroll
        for (int c = 0; c < 4; c++) acc[r][c] = 0ull;

    const int ka = t >> 4, ca = (t & 15) * 4;
    const int kw0 = t >> 5, cw0 = (t & 31) * 4;
    const int kw1 = (t + 256) >> 5, cw1 = ((t + 256) & 31) * 4;
    float4 av, wv0, wv1;
    av  = __ldcg((const float4*)&AT[(size_t)(k0 + ka) * 64 + ca]);
    wv0 = *(const float4*)&WT[(size_t)(k0 + kw0) * 2048 + col0 + cw0];
    wv1 = *(const float4*)&WT[(size_t)(k0 + kw1) * 2048 + col0 + cw1];

    for (int kb = 0; kb < klen; kb += 16) {
        *(float4*)&Ash[ka][ca] = av;
        *(float4*)&Wsh[kw0][cw0] = wv0;
        *(float4*)&Wsh[kw1][cw1] = wv1;
        __syncthreads();
        if (kb + 16 < klen) {
            int kn = k0 + kb + 16;
            av  = __ldcg((const float4*)&AT[(size_t)(kn + ka) * 64 + ca]);
            wv0 = *(const float4*)&WT[(size_t)(kn + kw0) * 2048 + col0 + cw0];
            wv1 = *(const float4*)&WT[(size_t)(kn + kw1) * 2048 + col0 + cw1];
        }
#pragma unroll
        for (int kk = 0; kk < 16; kk++) {
            float4 a4 = *(const float4*)&Ash[kk][rg];
            u64 as0 = splat2(a4.x), as1 = splat2(a4.y), as2 = splat2(a4.z), as3 = splat2(a4.w);
            const u64* wd = (const u64*)&Wsh[kk][cg];
            u64 w0 = wd[0], w1 = wd[1], w2 = wd[2], w3 = wd[3];
            acc[0][0] = ffma2(as0, w0, acc[0][0]); acc[0][1] = ffma2(as0, w1, acc[0][1]);
            acc[0][2] = ffma2(as0, w2, acc[0][2]); acc[0][3] = ffma2(as0, w3, acc[0][3]);
            acc[1][0] = ffma2(as1, w0, acc[1][0]); acc[1][1] = ffma2(as1, w1, acc[1][1]);
            acc[1][2] = ffma2(as1, w2, acc[1][2]); acc[1][3] = ffma2(as1, w3, acc[1][3]);
            acc[2][0] = ffma2(as2, w0, acc[2][0]); acc[2][1] = ffma2(as2, w1, acc[2][1]);
            acc[2][2] = ffma2(as2, w2, acc[2][2]); acc[2][3] = ffma2(as2, w3, acc[2][3]);
            acc[3][0] = ffma2(as3, w0, acc[3][0]); acc[3][1] = ffma2(as3, w1, acc[3][1]);
            acc[3][2] = ffma2(as3, w2, acc[3][2]); acc[3][3] = ffma2(as3, w3, acc[3][3]);
        }
        __syncthreads();
    }
#pragma unroll
    for (int r = 0; r < 4; r++) {
        float2 v0 = unpack2(acc[r][0]), v1 = unpack2(acc[r][1]);
        float2 v2 = unpack2(acc[r][2]), v3 = unpack2(acc[r][3]);
        float* d = &part[(size_t)(rg + r) * G4 + col0 + cg];
        *(float4*)d = make_float4(v0.x, v0.y, v1.x, v1.y);
        *(float4*)(d + 4) = make_float4(v2.x, v2.y, v3.x, v3.y);
    }
}

// ---------------- LSTM pointwise (optional split-bf16 emission) ----------------
static __device__ __forceinline__ void pointwise(
    const float* __restrict__ p1, int n1, const float* __restrict__ p2, int n2,
    const float* __restrict__ xadd,
    const float* __restrict__ bih, const float* __restrict__ bhh,
    float* __restrict__ c, float* __restrict__ hT1, float* __restrict__ hT2,
    float* __restrict__ hflat, u16* __restrict__ ahi, u16* __restrict__ alo, int strow)
{
    int idx = blockIdx.x * TPB + threadIdx.x;
    int b = idx >> 9, j = idx & 511;
    float g[4];
#pragma unroll
    for (int gi = 0; gi < 4; gi++) {
        int col = gi * 512 + j;
        size_t off = (size_t)b * G4 + col;
        float v = bih[col] + bhh[col];
        if (xadd) v += xadd[off];
        for (int s = 0; s < n1; s++) v += __ldcg(&p1[(size_t)s * PART + off]);
        for (int s = 0; s < n2; s++) v += __ldcg(&p2[(size_t)s * PART + off]);
        g[gi] = v;
    }
    float ig = sigmf(g[0]), fg = sigmf(g[1]), tg = tanhf(g[2]), og = sigmf(g[3]);
    float cn = fg * c[idx] + ig * tg;
    c[idx] = cn;
    float h = og * tanhf(cn);
    hT1[j * 64 + b] = h;
    if (hT2) hT2[j * 64 + b] = h;
    if (hflat) hflat[(size_t)b * 512 + j] = h;
    if (ahi) {
        __nv_bfloat16 hh = __float2bfloat16(h);
        __nv_bfloat16 hl = __float2bfloat16(h - __bfloat162float(hh));
        ahi[(size_t)(strow + b) * 512 + j] = *(u16*)&hh;
        alo[(size_t)(strow + b) * 512 + j] = *(u16*)&hl;
    }
}

// ---------------- attention (CTA = batch row b) ----------------
static __device__ __forceinline__ void attention(int b, float* hsh, float* ssh, float* ash) {
    int tid = threadIdx.x;
    for (int k = tid; k < 512; k += TPB) hsh[k] = __ldcg(&g_decA1T[(512 + k) * 64 + b]);
    __syncthreads();
    int w = tid >> 5, lane = tid & 31;
    for (int s = w; s < 64; s += 8) {
        const float* e = g_encouts + (size_t)s * 32768 + (size_t)b * 512;
        float d = 0.f;
#pragma unroll 4
        for (int k = lane; k < 512; k += 32) d += e[k] * hsh[k];
#pragma unroll
        for (int o = 16; o; o >>= 1) d += __shfl_down_sync(0xffffffffu, d, o);
        if (!lane) ssh[s] = d;
    }
    __syncthreads();
    if (tid < 32) {
        float s0 = ssh[tid], s1 = ssh[tid + 32];
        float m = fmaxf(s0, s1);
#pragma unroll
        for (int o = 16; o; o >>= 1) m = fmaxf(m, __shfl_xor_sync(0xffffffffu, m, o));
        float e0 = __expf(s0 - m), e1 = __expf(s1 - m);
        float sum = e0 + e1;
#pragma unroll
        for (int o = 16; o; o >>= 1) sum += __shfl_xor_sync(0xffffffffu, sum, o);
        float inv = 1.f / sum;
        ash[tid] = e0 * inv;
        ash[tid + 32] = e1 * inv;
    }
    __syncthreads();
    for (int j = tid; j < 512; j += TPB) {
        float acc = 0.f;
#pragma unroll 8
        for (int s = 0; s < 64; s++)
            acc += ash[s] * g_encouts[(size_t)s * 32768 + (size_t)b * 512 + j];
        g_decA0T[j * 64 + b] = acc;
    }
    __syncthreads();
}

// ---------------- persistent recurrence kernel ----------------
__global__ void __launch_bounds__(TPB, 1) recurrent(
    const float* __restrict__ ebih0, const float* __restrict__ ebhh0,
    const float* __restrict__ ebih1, const float* __restrict__ ebhh1,
    const float* __restrict__ dbih0, const float* __restrict__ dbhh0,
    const float* __restrict__ dbih1, const float* __restrict__ dbhh1)
{
    __shared__ __align__(16) float Ash[16][64];
    __shared__ __align__(16) float Wsh[16][128];
    __shared__ float hsh[512];
    __shared__ float ssh[64];
    __shared__ float ashm[64];
    const int bid = blockIdx.x;
    const int gid = bid * TPB + threadIdx.x;

    g_encA1T[gid] = 0.f;
    g_encA1T[gid + 32768] = 0.f;
    g_c0[gid] = 0.f;
    g_c1[gid] = 0.f;
    gbar();

    const int ks = bid >> 4;
    const int colJ = (bid & 15) * 128;

    tile_gemm(Ash, Wsh, g_encA1T, g_Wenc0T, ks * 64, 64, colJ, g_partB + (size_t)ks * PART);
    gbar();

    // ---- encoder: 2 phases per step ----
    for (int st = 0; st < SLEN; st++) {
        pointwise(g_partB, 8, nullptr, 0, g_Xenc + (size_t)st * PART, ebih0, ebhh0,
                  g_c0, g_encA1T, nullptr, nullptr, nullptr, nullptr, 0);
        if (st > 0)
            pointwise(g_partA, 8, nullptr, 0, nullptr, ebih1, ebhh1,
                      g_c1, g_encA1T + 512 * 64, nullptr,
                      g_encouts + (size_t)(st - 1) * 32768, nullptr, nullptr, 0);
        gbar();
        tile_gemm(Ash, Wsh, g_encA1T, g_Wenc1T, ks * 128, 128, colJ, g_partA + (size_t)ks * PART);
        if (st < SLEN - 1)
            tile_gemm(Ash, Wsh, g_encA1T, g_Wenc0T, ks * 64, 64, colJ, g_partB + (size_t)ks * PART);
        gbar();
    }
    pointwise(g_partA, 8, nullptr, 0, nullptr, ebih1, ebhh1,
              g_c1, g_encA1T + 512 * 64, nullptr,
              g_encouts + (size_t)(SLEN - 1) * 32768, nullptr, nullptr, 0);
    gbar();

    // transition
    {
        int j = gid >> 6, b = gid & 63;
        float h0 = __ldcg(&g_encA1T[j * 64 + b]);
        float h1 = __ldcg(&g_encA1T[(512 + j) * 64 + b]);
        g_decA0T[(512 + j) * 64 + b] = h0;
        g_decA1T[j * 64 + b] = h0;
        g_decA1T[(512 + j) * 64 + b] = h1;
    }
    gbar();

    // ---- decoder: overlapped 5-phase schedule ----
    for (int st = 0; st < DSTEPS; st++) {
        // phase A: attention (0..63) || gemm1 h1-half K=[512,1024) (64..127 -> partB[4..7])
        if (bid < 64) {
            attention(bid, hsh, ssh, ashm);
        } else {
            int ks2 = (bid - 64) >> 4;          // 0..3
            int col2 = ((bid - 64) & 15) * 128;
            tile_gemm(Ash, Wsh, g_decA1T, g_Wdec1T, 512 + ks2 * 128, 128, col2,
                      g_partB + (size_t)(4 + ks2) * PART);
        }
        gbar();
        // phase B: gemm0 FULL K=1024 (128 CTAs, K=128 each) -> partA
        tile_gemm(Ash, Wsh, g_decA0T, g_Wdec0T, ks * 128, 128, colJ, g_partA + (size_t)ks * PART);
        gbar();
        // phase C: pointwise L0
        pointwise(g_partA, 8, nullptr, 0, g_Xdec + (size_t)st * PART, dbih0, dbhh0,
                  g_c0, g_decA0T + 512 * 64, g_decA1T, nullptr, nullptr, nullptr, 0);
        gbar();
        // phase D: gemm1 h0-half K=[0,512) (128 CTAs, K=64 each) -> partA (reuse)
        tile_gemm(Ash, Wsh, g_decA1T, g_Wdec1T, ks * 64, 64, colJ, g_partA + (size_t)ks * PART);
        gbar();
        // phase E: pointwise L1 (partA[0..7] K=64-chunks + partB[4..7] K=128-chunks)
        pointwise(g_partA, 8, g_partB + 4 * (size_t)PART, 4, nullptr, dbih1, dbhh1,
                  g_c1, g_decA1T + 512 * 64, nullptr, nullptr,
                  g_Ahi, g_Alo, st * 64);
        gbar();
    }
}

// ---------------- fused init ----------------
__global__ void init_gather(const int* __restrict__ src, const int* __restrict__ trg,
                            const float* __restrict__ enc_emb, const float* __restrict__ dec_emb,
                            float* __restrict__ out) {
    int blk = blockIdx.x;
    if (blk < 2032) {
        int row = blk * 4 + (threadIdx.x >> 6);
        int t4 = threadIdx.x & 63;
        if (row < SLEN * BATCH) {
            int tok = src[row];
            reinterpret_cast<float4*>(g_embS + (size_t)row * EDIM)[t4] =
                reinterpret_cast<const float4*>(enc_emb + (size_t)tok * EDIM)[t4];
        } else {
            int r = row - SLEN * BATCH;
            int tok = trg[r];
            reinterpret_cast<float4*>(g_embT + (size_t)r * EDIM)[t4] =
                reinterpret_cast<const float4*>(dec_emb + (size_t)tok * EDIM)[t4];
        }
    } else {
        int i = (blk - 2032) * 256 + threadIdx.x;
        if (i < BATCH * OUTV) out[i] = 0.0f;
    }
}

// ---------------- transpose pack ----------------
__global__ void transpose_all(
    const float* __restrict__ eWhh0, const float* __restrict__ eWih1, const float* __restrict__ eWhh1,
    const float* __restrict__ dWih0, const float* __restrict__ dWhh0,
    const float* __restrict__ dWih1, const float* __restrict__ dWhh1,
    float* __restrict__ W0T, float* __restrict__ W1T,
    float* __restrict__ D0T, float* __restrict__ D1T)
{
    __shared__ float tile[32][33];
    const float* src; int lds = 512, coloff = 0, dstk0 = 0; float* dst;
    switch (blockIdx.z) {
        case 0: src = eWhh0; dst = W0T; break;
        case 1: src = eWih1; dst = W1T; break;
        case 2: src = eWhh1; dst = W1T; dstk0 = 512; break;
        case 3: src = dWih0; dst = D0T; lds = 768; coloff = 256; break;
        case 4: src = dWhh0; dst = D0T; dstk0 = 512; break;
        case 5: src = dWih1; dst = D1T; break;
        default: src = dWhh1; dst = D1T; dstk0 = 512; break;
    }
    int rb = blockIdx.x * 32, kb = blockIdx.y * 32;
    int tx = threadIdx.x & 31, ty = threadIdx.x >> 5;
#pragma unroll
    for (int i = 0; i < 4; i++)
        tile[ty + i * 8][tx] = src[(size_t)(rb + ty + i * 8) * lds + coloff + kb + tx];
    __syncthreads();
#pragma unroll
    for (int i = 0; i < 4; i++)
        dst[(size_t)(dstk0 + kb + ty + i * 8) * 2048 + rb + tx] = tile[tx][ty + i * 8];
}

// ---------------- big GEMM core (f32x2, proj only) ----------------
static __device__ __forceinline__ void gemm_core(
    const float* __restrict__ A, int lda, const float* __restrict__ W, int ldw,
    float* __restrict__ C, int M, int N, int K, int bx, int by)
{
    __shared__ __align__(16) float Ash[16][132];
    __shared__ __align__(16) float Wsh[16][132];
    int row0 = by * 128, col0 = bx * 128;
    int tid = threadIdx.x;
    int tx = tid & 15, ty = tid >> 4;
    int lr = tid >> 2, lk4 = (tid & 3) * 4;
    u64 acc[4][8];
#pragma unroll
    for (int p = 0; p < 4; p++)
#pragma unroll
        for (int j = 0; j < 8; j++) acc[p][j] = 0ull;

    float4 avr[2], wvr[2];
#pragma unroll
    for (int h = 0; h < 2; h++) {
        int rr = lr + h * 64;
        int r = row0 + rr, c = col0 + rr;
        avr[h] = (r < M) ? *(const float4*)&A[(size_t)r * lda + lk4] : make_float4(0, 0, 0, 0);
        wvr[h] = (c < N) ? *(const float4*)&W[(size_t)c * ldw + lk4] : make_float4(0, 0, 0, 0);
    }
    for (int kb = 0; kb < K; kb += 16) {
#pragma unroll
        for (int h = 0; h < 2; h++) {
            int rr = lr + h * 64;
            Ash[lk4 + 0][rr] = avr[h].x; Ash[lk4 + 1][rr] = avr[h].y;
            Ash[lk4 + 2][rr] = avr[h].z; Ash[lk4 + 3][rr] = avr[h].w;
            Wsh[lk4 + 0][rr] = wvr[h].x; Wsh[lk4 + 1][rr] = wvr[h].y;
            Wsh[lk4 + 2][rr] = wvr[h].z; Wsh[lk4 + 3][rr] = wvr[h].w;
        }
        __syncthreads();
        if (kb + 16 < K) {
            int kn = kb + 16;
#pragma unroll
            for (int h = 0; h < 2; h++) {
                int rr = lr + h * 64;
                int r = row0 + rr, c = col0 + rr;
                avr[h] = (r < M) ? *(const float4*)&A[(size_t)r * lda + kn + lk4] : make_float4(0, 0, 0, 0);
                wvr[h] = (c < N) ? *(const float4*)&W[(size_t)c * ldw + kn + lk4] : make_float4(0, 0, 0, 0);
            }
        }
#pragma unroll
        for (int kk = 0; kk < 16; kk++) {
            const u64* ap = (const u64*)&Ash[kk][ty * 8];
            u64 a0 = ap[0], a1 = ap[1], a2 = ap[2], a3 = ap[3];
            float4 w0 = *(const float4*)&Wsh[kk][tx * 8];
            float4 w1 = *(const float4*)&Wsh[kk][tx * 8 + 4];
            u64 ws[8];
            ws[0] = splat2(w0.x); ws[1] = splat2(w0.y); ws[2] = splat2(w0.z); ws[3] = splat2(w0.w);
            ws[4] = splat2(w1.x); ws[5] = splat2(w1.y); ws[6] = splat2(w1.z); ws[7] = splat2(w1.w);
#pragma unroll
            for (int j = 0; j < 8; j++) {
                acc[0][j] = ffma2(a0, ws[j], acc[0][j]);
                acc[1][j] = ffma2(a1, ws[j], acc[1][j]);
                acc[2][j] = ffma2(a2, ws[j], acc[2][j]);
                acc[3][j] = ffma2(a3, ws[j], acc[3][j]);
            }
        }
        __syncthreads();
    }
#pragma unroll
    for (int p = 0; p < 4; p++) {
        float2 v[8];
#pragma unroll
        for (int j = 0; j < 8; j++) v[j] = unpack2(acc[p][j]);
        int r = row0 + ty * 8 + p * 2;
        if (r < M) {
#pragma unroll
            for (int j = 0; j < 8; j++) {
                int c = col0 + tx * 8 + j;
                if (c < N) C[(size_t)r * G4 + c] = v[j].x;
            }
        }
        if (r + 1 < M) {
#pragma unroll
            for (int j = 0; j < 8; j++) {
                int c = col0 + tx * 8 + j;
                if (c < N) C[(size_t)(r + 1) * G4 + c] = v[j].y;
            }
        }
    }
}

__global__ void __launch_bounds__(256) proj_gemm(
    const float* __restrict__ embS, const float* __restrict__ eWih0,
    const float* __restrict__ embT, const float* __restrict__ dWih0,
    float* __restrict__ Xenc, float* __restrict__ Xdec)
{
    if (blockIdx.z == 0)
        gemm_core(embS, EDIM, eWih0, EDIM, Xenc, SLEN * BATCH, G4, EDIM,
                  blockIdx.x, blockIdx.y);
    else
        gemm_core(embT, EDIM, dWih0, 768, Xdec, DSTEPS * BATCH, G4, EDIM,
                  blockIdx.x, blockIdx.y);
}

// ---------------- split fp32 -> bf16 hi/lo (W only) ----------------
__global__ void split_bf16(const float* __restrict__ fcW) {
    int i = blockIdx.x * 256 + threadIdx.x;
    if (i < OUTV * 512) {
        float x = fcW[i];
        __nv_bfloat16 h = __float2bfloat16(x);
        __nv_bfloat16 l = __float2bfloat16(x - __bfloat162float(h));
        g_Whi[i] = *(u16*)&h;
        g_Wlo[i] = *(u16*)&l;
    }
}

// ---------------- FC via split-bf16 mma.sync (m16n8k16), kc=32 ----------------
static __device__ __forceinline__ void mma16816(float* d, const u32* a, const u32* b) {
    asm volatile(
        "mma.sync.aligned.m16n8k16.row.col.f32.bf16.bf16.f32 "
        "{%0,%1,%2,%3}, {%4,%5,%6,%7}, {%8,%9}, {%0,%1,%2,%3};\n"
        : "+f"(d[0]), "+f"(d[1]), "+f"(d[2]), "+f"(d[3])
        : "r"(a[0]), "r"(a[1]), "r"(a[2]), "r"(a[3]), "r"(b[0]), "r"(b[1]));
}

__global__ void __launch_bounds__(256) fc_hmma(const float* __restrict__ bias,
                                               float* __restrict__ out) {
    __shared__ __align__(16) u16 sA[2][128][32];
    __shared__ __align__(16) u16 sW[2][128][32];
    const int m0 = blockIdx.y * 128, n0 = blockIdx.x * 128;
    const int tid = threadIdx.x;
    const int w = tid >> 5, lane = tid & 31;
    const int wr = (w & 3) * 32;
    const int wc = (w >> 2) * 64;
    const int lg = lane >> 2, lk = (lane & 3) * 2;

    float acc[2][8][4];
#pragma unroll
    for (int mt = 0; mt < 2; mt++)
#pragma unroll
        for (int nt = 0; nt < 8; nt++)
#pragma unroll
            for (int q = 0; q < 4; q++) acc[mt][nt][q] = 0.f;

    const int lrow = tid >> 1, lhalf = (tid & 1) * 16;
    for (int kc = 0; kc < 512; kc += 32) {
        {
            int gr = m0 + lrow;
            float4 z = make_float4(0, 0, 0, 0);
            float4 ah0 = z, ah1 = z, al0 = z, al1 = z;
            if (gr < FCM) {
                ah0 = *(const float4*)&g_Ahi[(size_t)gr * 512 + kc + lhalf];
                ah1 = *(const float4*)&g_Ahi[(size_t)gr * 512 + kc + lhalf + 8];
                al0 = *(const float4*)&g_Alo[(size_t)gr * 512 + kc + lhalf];
                al1 = *(const float4*)&g_Alo[(size_t)gr * 512 + kc + lhalf + 8];
            }
            *(float4*)&sA[0][lrow][lhalf] = ah0;
            *(float4*)&sA[0][lrow][lhalf + 8] = ah1;
            *(float4*)&sA[1][lrow][lhalf] = al0;
            *(float4*)&sA[1][lrow][lhalf + 8] = al1;
            int gc = n0 + lrow;
            float4 wh0 = z, wh1 = z, wl0 = z, wl1 = z;
            if (gc < OUTV) {
                wh0 = *(const float4*)&g_Whi[(size_t)gc * 512 + kc + lhalf];
                wh1 = *(const float4*)&g_Whi[(size_t)gc * 512 + kc + lhalf + 8];
                wl0 = *(const float4*)&g_Wlo[(size_t)gc * 512 + kc + lhalf];
                wl1 = *(const float4*)&g_Wlo[(size_t)gc * 512 + kc + lhalf + 8];
            }
            *(float4*)&sW[0][lrow][lhalf] = wh0;
            *(float4*)&sW[0][lrow][lhalf + 8] = wh1;
            *(float4*)&sW[1][lrow][lhalf] = wl0;
            *(float4*)&sW[1][lrow][lhalf + 8] = wl1;
        }
        __syncthreads();
#pragma unroll
        for (int sub = 0; sub < 32; sub += 16) {
            u32 af[2][2][4], bf[2][8][2];
#pragma unroll
            for (int s = 0; s < 2; s++)
#pragma unroll
                for (int mt = 0; mt < 2; mt++) {
                    int r0 = wr + mt * 16 + lg;
                    af[s][mt][0] = *(const u32*)&sA[s][r0][sub + lk];
                    af[s][mt][1] = *(const u32*)&sA[s][r0 + 8][sub + lk];
                    af[s][mt][2] = *(const u32*)&sA[s][r0][sub + lk + 8];
                    af[s][mt][3] = *(const u32*)&sA[s][r0 + 8][sub + lk + 8];
                }
#pragma unroll
            for (int s = 0; s < 2; s++)
#pragma unroll
                for (int nt = 0; nt < 8; nt++) {
                    int c0 = wc + nt * 8 + lg;
                    bf[s][nt][0] = *(const u32*)&sW[s][c0][sub + lk];
                    bf[s][nt][1] = *(const u32*)&sW[s][c0][sub + lk + 8];
                }
#pragma unroll
            for (int mt = 0; mt < 2; mt++)
#pragma unroll
                for (int nt = 0; nt < 8; nt++) {
                    mma16816(acc[mt][nt], af[0][mt], bf[0][nt]);
                    mma16816(acc[mt][nt], af[0][mt], bf[1][nt]);
                    mma16816(acc[mt][nt], af[1][mt], bf[0][nt]);
                }
        }
        __syncthreads();
    }
#pragma unroll
    for (int mt = 0; mt < 2; mt++)
#pragma unroll
        for (int nt = 0; nt < 8; nt++) {
            int r = m0 + wr + mt * 16 + lg;
            int c = n0 + wc + nt * 8 + lk;
            float* d = acc[mt][nt];
            if (r < FCM) {
                if (c < OUTV)     out[(size_t)r * OUTV + c]     = d[0] + bias[c];
                if (c + 1 < OUTV) out[(size_t)r * OUTV + c + 1] = d[1] + bias[c + 1];
            }
            if (r + 8 < FCM) {
                if (c < OUTV)     out[(size_t)(r + 8) * OUTV + c]     = d[2] + bias[c];
                if (c + 1 < OUTV) out[(size_t)(r + 8) * OUTV + c + 1] = d[3] + bias[c + 1];
            }
        }
}

// ---------------- host ----------------
extern "C" void kernel_launch(void* const* d_in, const int* in_sizes, int n_in,
                              void* d_out, int out_size) {
    const int* src = (const int*)d_in[0];
    const int* trg = (const int*)d_in[1];
    const float* enc_emb = (const float*)d_in[2];
    const float* eWih0 = (const float*)d_in[3];
    const float* eWhh0 = (const float*)d_in[4];
    const float* ebih0 = (const float*)d_in[5];
    const float* ebhh0 = (const float*)d_in[6];
    const float* eWih1 = (const float*)d_in[7];
    const float* eWhh1 = (const float*)d_in[8];
    const float* ebih1 = (const float*)d_in[9];
    const float* ebhh1 = (const float*)d_in[10];
    const float* dec_emb = (const float*)d_in[11];
    const float* dWih0 = (const float*)d_in[12];
    const float* dWhh0 = (const float*)d_in[13];
    const float* dbih0 = (const float*)d_in[14];
    const float* dbhh0 = (const float*)d_in[15];
    const float* dWih1 = (const float*)d_in[16];
    const float* dWhh1 = (const float*)d_in[17];
    const float* dbih1 = (const float*)d_in[18];
    const float* dbhh1 = (const float*)d_in[19];
    const float* fcW = (const float*)d_in[20];
    const float* fcb = (const float*)d_in[21];
    float* out = (float*)d_out;

    float *Xenc, *Xdec, *embS, *embT;
    float *W0T, *W1T, *D0T, *D1T;
    cudaGetSymbolAddress((void**)&Xenc, g_Xenc);
    cudaGetSymbolAddress((void**)&Xdec, g_Xdec);
    cudaGetSymbolAddress((void**)&embS, g_embS);
    cudaGetSymbolAddress((void**)&embT, g_embT);
    cudaGetSymbolAddress((void**)&W0T, g_Wenc0T);
    cudaGetSymbolAddress((void**)&W1T, g_Wenc1T);
    cudaGetSymbolAddress((void**)&D0T, g_Wdec0T);
    cudaGetSymbolAddress((void**)&D1T, g_Wdec1T);

    // 1: fused zero + gather
    init_gather<<<2032 + 1500, 256>>>(src, trg, enc_emb, dec_emb, out);
    // 2: weight transposes
    transpose_all<<<dim3(64, 16, 7), 256>>>(eWhh0, eWih1, eWhh1, dWih0, dWhh0, dWih1, dWhh1,
                                            W0T, W1T, D0T, D1T);
    // 3: input projections
    proj_gemm<<<dim3(16, 32, 2), 256>>>(embS, eWih0, embT, dWih0, Xenc, Xdec);
    // 4: persistent recurrence (profiled slot)
    recurrent<<<NCTA, TPB>>>(ebih0, ebhh0, ebih1, ebhh1, dbih0, dbhh0, dbih1, dbhh1);
    // 5: split W into bf16 hi/lo
    split_bf16<<<(OUTV * 512 + 255) / 256, 256>>>(fcW);
    // 6: tensor-core FC
    fc_hmma<<<dim3(47, 32), 256>>>(fcb, out + (size_t)BATCH * OUTV);
}